// round 1
// baseline (speedup 1.0000x reference)
#include <cuda_runtime.h>

#define NPOS 16384   // 128*128 guide positions
#define LPOS 1024    // 32*32 low positions
#define DMODEL 512
#define NH 8
#define DM 64

// Scratch (static device globals — no allocation APIs allowed)
__device__ float g_Q [NPOS * DMODEL];
__device__ float g_K [LPOS * DMODEL];
__device__ float g_V [LPOS * DMODEL];
__device__ float g_M1[NPOS * DMODEL];
__device__ float g_M2[NPOS * DMODEL];

// ---------------------------------------------------------------------------
// SGEMM: C[m][n] = sum_k A(k,m) * B[n][k]
//   AKM=1: A stored K-major, A[k*M + m]   (input feature maps: [channel][pos])
//   AKM=0: A stored M-major, A[m*K + k]   (msg rows)
//   B always row-major [N][K]             (weight matrices W[o][c])
// 128x128 block tile, BK=8, 256 threads, 8x8 per-thread microtile.
// ---------------------------------------------------------------------------
template<int AKM>
__global__ __launch_bounds__(256, 2)
void sgemm_kernel(const float* __restrict__ A, const float* __restrict__ B,
                  float* __restrict__ C, int M, int N, int K)
{
    __shared__ float As[8][128];
    __shared__ float Bs[8][128];

    const int tid = threadIdx.x;
    const int bm0 = blockIdx.y * 128;
    const int bn0 = blockIdx.x * 128;
    const int tm0 = (tid >> 4) * 8;
    const int tn0 = (tid & 15) * 8;

    float acc[8][8];
#pragma unroll
    for (int i = 0; i < 8; i++)
#pragma unroll
        for (int j = 0; j < 8; j++) acc[i][j] = 0.f;

    for (int k0 = 0; k0 < K; k0 += 8) {
        if (AKM) {
            // A[k][m], rows contiguous in m: coalesced float4
            const int krow = tid >> 5;
            const int mc   = tid & 31;
            float4 v = *(const float4*)(A + (size_t)(k0 + krow) * M + bm0 + mc * 4);
            *(float4*)&As[krow][mc * 4] = v;
        } else {
            // A[m][k]: transpose on load
            const int mrow = tid >> 1;
            const int kc   = (tid & 1) * 4;
            float4 v = *(const float4*)(A + (size_t)(bm0 + mrow) * K + k0 + kc);
            As[kc + 0][mrow] = v.x;
            As[kc + 1][mrow] = v.y;
            As[kc + 2][mrow] = v.z;
            As[kc + 3][mrow] = v.w;
        }
        {
            // B[n][k]: transpose on load
            const int nrow = tid >> 1;
            const int kc   = (tid & 1) * 4;
            float4 v = *(const float4*)(B + (size_t)(bn0 + nrow) * K + k0 + kc);
            Bs[kc + 0][nrow] = v.x;
            Bs[kc + 1][nrow] = v.y;
            Bs[kc + 2][nrow] = v.z;
            Bs[kc + 3][nrow] = v.w;
        }
        __syncthreads();

#pragma unroll
        for (int kk = 0; kk < 8; kk++) {
            float a[8], b[8];
            *(float4*)&a[0] = *(float4*)&As[kk][tm0];
            *(float4*)&a[4] = *(float4*)&As[kk][tm0 + 4];
            *(float4*)&b[0] = *(float4*)&Bs[kk][tn0];
            *(float4*)&b[4] = *(float4*)&Bs[kk][tn0 + 4];
#pragma unroll
            for (int i = 0; i < 8; i++)
#pragma unroll
                for (int j = 0; j < 8; j++)
                    acc[i][j] += a[i] * b[j];
        }
        __syncthreads();
    }

#pragma unroll
    for (int i = 0; i < 8; i++) {
        float* crow = C + (size_t)(bm0 + tm0 + i) * N + bn0 + tn0;
        *(float4*)(crow)     = make_float4(acc[i][0], acc[i][1], acc[i][2], acc[i][3]);
        *(float4*)(crow + 4) = make_float4(acc[i][4], acc[i][5], acc[i][6], acc[i][7]);
    }
}

// ---------------------------------------------------------------------------
// Windowed attention. One block per 4x4 guide tile: all 16 guide positions in
// tile (ty,tx) share window rows clip(ty-1..ty+1), cols clip(tx-1..tx+1).
// K/V 9x512 vectors staged in smem; 128 threads = 16 pos x 8 heads.
// msg[n][h*64+e] = softmax_k( q.K_k / 8 ) . V_k
// ---------------------------------------------------------------------------
__global__ __launch_bounds__(128)
void attn_kernel(const float* __restrict__ Q, const float* __restrict__ Km,
                 const float* __restrict__ Vm, float* __restrict__ msg)
{
    __shared__ float Ks[9][512];
    __shared__ float Vs[9][512];

    const int tx = blockIdx.x;   // 0..31 guide tile col
    const int ty = blockIdx.y;   // 0..31 guide tile row
    const int tid = threadIdx.x;

    // Stage 9 K and 9 V vectors (4608 floats each) with float4 loads
    for (int idx = tid; idx < 9 * 128; idx += 128) {
        const int k  = idx >> 7;       // window slot 0..8
        const int c4 = idx & 127;      // float4 index within 512
        const int yy = min(max(ty - 1 + k / 3, 0), 31);
        const int xx = min(max(tx - 1 + k % 3, 0), 31);
        const int p  = yy * 32 + xx;
        ((float4*)&Ks[k][0])[c4] = ((const float4*)(Km + (size_t)p * 512))[c4];
        ((float4*)&Vs[k][0])[c4] = ((const float4*)(Vm + (size_t)p * 512))[c4];
    }
    __syncthreads();

    const int head = tid >> 4;                 // 0..7
    const int pos  = tid & 15;                 // 0..15
    const int n = (ty * 4 + (pos >> 2)) * 128 + tx * 4 + (pos & 3);

    const float4* q4 = (const float4*)(Q + (size_t)n * 512 + head * 64);

    float acc[9];
#pragma unroll
    for (int k = 0; k < 9; k++) acc[k] = 0.f;

#pragma unroll 4
    for (int e = 0; e < 16; e++) {
        float4 qv = q4[e];
#pragma unroll
        for (int k = 0; k < 9; k++) {
            float4 kv = ((const float4*)&Ks[k][head * 64])[e];
            acc[k] += qv.x * kv.x + qv.y * kv.y + qv.z * kv.z + qv.w * kv.w;
        }
    }

    float mx = acc[0];
#pragma unroll
    for (int k = 1; k < 9; k++) mx = fmaxf(mx, acc[k]);
    float s = 0.f;
#pragma unroll
    for (int k = 0; k < 9; k++) { acc[k] = __expf(0.125f * (acc[k] - mx)); s += acc[k]; }
    const float inv = 1.f / s;
#pragma unroll
    for (int k = 0; k < 9; k++) acc[k] *= inv;

    float4* out4 = (float4*)(msg + (size_t)n * 512 + head * 64);
#pragma unroll 4
    for (int e = 0; e < 16; e++) {
        float4 o = make_float4(0.f, 0.f, 0.f, 0.f);
#pragma unroll
        for (int k = 0; k < 9; k++) {
            float4 vv = ((const float4*)&Vs[k][head * 64])[e];
            o.x += acc[k] * vv.x;
            o.y += acc[k] * vv.y;
            o.z += acc[k] * vv.z;
            o.w += acc[k] * vv.w;
        }
        out4[e] = o;
    }
}

// ---------------------------------------------------------------------------
// LayerNorm over d=512 per position + transpose to channel-major output.
// Block handles 16 rows; warp-per-row reductions; smem staging for coalesced
// transposed stores. Output: out[o*16384 + n].
// ---------------------------------------------------------------------------
__global__ __launch_bounds__(256)
void ln_kernel(const float* __restrict__ X, const float* __restrict__ gamma,
               const float* __restrict__ beta, float* __restrict__ out)
{
    __shared__ float sm[16 * 513];

    const int nb   = blockIdx.x * 16;
    const int warp = threadIdx.x >> 5;
    const int lane = threadIdx.x & 31;

    for (int r = warp; r < 16; r += 8) {
        const int n = nb + r;
        const float* row = X + (size_t)n * 512;
        float v[16];
        float s = 0.f;
#pragma unroll
        for (int j = 0; j < 16; j++) { v[j] = row[lane + 32 * j]; s += v[j]; }
#pragma unroll
        for (int o = 16; o > 0; o >>= 1) s += __shfl_xor_sync(0xffffffffu, s, o);
        const float mu = s * (1.f / 512.f);
        float q = 0.f;
#pragma unroll
        for (int j = 0; j < 16; j++) { float d = v[j] - mu; q += d * d; }
#pragma unroll
        for (int o = 16; o > 0; o >>= 1) q += __shfl_xor_sync(0xffffffffu, q, o);
        const float rstd = rsqrtf(q * (1.f / 512.f) + 1e-5f);
#pragma unroll
        for (int j = 0; j < 16; j++) {
            const int o = lane + 32 * j;
            sm[r * 513 + o] = (v[j] - mu) * rstd * gamma[o] + beta[o];
        }
    }
    __syncthreads();

    // Transposed store: lane groups write 16 consecutive n per channel o
    const int i  = threadIdx.x & 15;
    const int ob = threadIdx.x >> 4;
    for (int o = ob; o < 512; o += 16)
        out[(size_t)o * 16384 + nb + i] = sm[i * 513 + o];
}

// ---------------------------------------------------------------------------
// Launch. Inputs (metadata order): low_feats[512*1024] (channel-major),
// guide_feats[512*16384] (channel-major), Wq, Wk, Wv, Wm [512*512 row-major
// as W[o][c]], gamma[512], beta[512]. Output: float[512*16384] channel-major.
// ---------------------------------------------------------------------------
extern "C" void kernel_launch(void* const* d_in, const int* in_sizes, int n_in,
                              void* d_out, int out_size)
{
    const float* low   = (const float*)d_in[0];
    const float* guide = (const float*)d_in[1];
    const float* Wq    = (const float*)d_in[2];
    const float* Wk    = (const float*)d_in[3];
    const float* Wv    = (const float*)d_in[4];
    const float* Wm    = (const float*)d_in[5];
    const float* gamma = (const float*)d_in[6];
    const float* beta  = (const float*)d_in[7];
    float* out = (float*)d_out;

    float *Q, *K, *V, *M1, *M2;
    cudaGetSymbolAddress((void**)&Q,  g_Q);
    cudaGetSymbolAddress((void**)&K,  g_K);
    cudaGetSymbolAddress((void**)&V,  g_V);
    cudaGetSymbolAddress((void**)&M1, g_M1);
    cudaGetSymbolAddress((void**)&M2, g_M2);

    // Q = guide^T @ Wq^T   (A K-major)
    sgemm_kernel<1><<<dim3(4, 128), 256>>>(guide, Wq, Q, NPOS, DMODEL, DMODEL);
    // K/V = low^T @ Wk^T / Wv^T
    sgemm_kernel<1><<<dim3(4, 8), 256>>>(low, Wk, K, LPOS, DMODEL, DMODEL);
    sgemm_kernel<1><<<dim3(4, 8), 256>>>(low, Wv, V, LPOS, DMODEL, DMODEL);
    // Windowed attention -> M1[n][d]
    attn_kernel<<<dim3(32, 32), 128>>>(Q, K, V, M1);
    // M2 = M1 @ Wm^T   (A M-major)
    sgemm_kernel<0><<<dim3(4, 128), 256>>>(M1, Wm, M2, NPOS, DMODEL, DMODEL);
    // LayerNorm + transpose to channel-major output
    ln_kernel<<<1024, 256>>>(M2, gamma, beta, out);
}

// round 2
// speedup vs baseline: 1.3651x; 1.3651x over previous
#include <cuda_runtime.h>

#define NPOS 16384   // 128*128 guide positions
#define LPOS 1024    // 32*32 low positions
#define DMODEL 512

// Scratch (static device globals — no allocation APIs allowed)
__device__ float g_Q [NPOS * DMODEL];
__device__ float g_K [LPOS * DMODEL];
__device__ float g_V [LPOS * DMODEL];
__device__ float g_M1[NPOS * DMODEL];
__device__ float g_M2[NPOS * DMODEL];

// ---------------------------------------------------------------------------
// f32x2 SGEMM: C[m][n] = sum_k A(k,m) * B[n][k]
//   AKM=1: A stored K-major, A[k*M + m]   (feature maps: [channel][pos])
//   AKM=0: A stored M-major, A[m*K + k]
//   B row-major [N][K] (weights W[o][c]); dual-B via blockIdx.z (B0/C0,B1/C1)
// BMxBN block tile, BK=8, 128 threads, TMxTN per-thread microtile with
// packed fma.rn.f32x2 accumulation (2 fp32 MACs per fma-pipe slot).
// Double-buffered smem, register prefetch, one __syncthreads per k-tile.
// ---------------------------------------------------------------------------
template<int AKM, int BM, int BN, int TM, int TN>
__global__ __launch_bounds__(128, 2)
void sgemm2_kernel(const float* __restrict__ A,
                   const float* __restrict__ B0, const float* __restrict__ B1,
                   float* __restrict__ C0, float* __restrict__ C1,
                   int M, int N, int K)
{
    constexpr int LA = BM * 8 / (128 * 4);   // float4 A-loads per thread
    constexpr int LB = BN * 8 / (128 * 4);   // float4 B-loads per thread
    constexpr int TN2 = TN / 2;

    __shared__ float As[2][8][BM];
    __shared__ float Bs[2][8][BN];

    const float* B = (blockIdx.z == 0) ? B0 : B1;
    float*       C = (blockIdx.z == 0) ? C0 : C1;

    const int tid = threadIdx.x;
    const int bm0 = blockIdx.y * BM;
    const int bn0 = blockIdx.x * BN;
    const int tm0 = (tid & 15) * TM;
    const int tn0 = (tid >> 4) * TN;

    unsigned long long acc[TM][TN2];
#pragma unroll
    for (int i = 0; i < TM; i++)
#pragma unroll
        for (int j = 0; j < TN2; j++) acc[i][j] = 0ull;

    float4 pa[LA], pb[LB];

    auto loadA = [&](int k0) {
#pragma unroll
        for (int it = 0; it < LA; it++) {
            const int idx = tid + 128 * it;
            if (AKM) {
                const int k  = idx / (BM / 4);
                const int mc = idx % (BM / 4);
                pa[it] = *(const float4*)(A + (size_t)(k0 + k) * M + bm0 + mc * 4);
            } else {
                const int mr = idx >> 1;
                const int kc = (idx & 1) * 4;
                pa[it] = *(const float4*)(A + (size_t)(bm0 + mr) * K + k0 + kc);
            }
        }
    };
    auto storeA = [&](int buf) {
#pragma unroll
        for (int it = 0; it < LA; it++) {
            const int idx = tid + 128 * it;
            if (AKM) {
                const int k  = idx / (BM / 4);
                const int mc = idx % (BM / 4);
                *(float4*)&As[buf][k][mc * 4] = pa[it];
            } else {
                const int mr = idx >> 1;
                const int kc = (idx & 1) * 4;
                As[buf][kc + 0][mr] = pa[it].x;
                As[buf][kc + 1][mr] = pa[it].y;
                As[buf][kc + 2][mr] = pa[it].z;
                As[buf][kc + 3][mr] = pa[it].w;
            }
        }
    };
    auto loadB = [&](int k0) {
#pragma unroll
        for (int it = 0; it < LB; it++) {
            const int idx = tid + 128 * it;
            const int nr = idx >> 1;
            const int kc = (idx & 1) * 4;
            pb[it] = *(const float4*)(B + (size_t)(bn0 + nr) * K + k0 + kc);
        }
    };
    auto storeB = [&](int buf) {
#pragma unroll
        for (int it = 0; it < LB; it++) {
            const int idx = tid + 128 * it;
            const int nr = idx >> 1;
            const int kc = (idx & 1) * 4;
            Bs[buf][kc + 0][nr] = pb[it].x;
            Bs[buf][kc + 1][nr] = pb[it].y;
            Bs[buf][kc + 2][nr] = pb[it].z;
            Bs[buf][kc + 3][nr] = pb[it].w;
        }
    };

    loadA(0); loadB(0);
    storeA(0); storeB(0);
    __syncthreads();

    int buf = 0;
    for (int k0 = 0; k0 < K; k0 += 8) {
        const bool nxt = (k0 + 8) < K;
        if (nxt) { loadA(k0 + 8); loadB(k0 + 8); }

#pragma unroll
        for (int kk = 0; kk < 8; kk++) {
            float a[TM];
#pragma unroll
            for (int i = 0; i < TM; i += 4)
                *(float4*)&a[i] = *(const float4*)&As[buf][kk][tm0 + i];

            unsigned long long a2[TM];
#pragma unroll
            for (int i = 0; i < TM; i++)
                asm("mov.b64 %0, {%1, %1};" : "=l"(a2[i]) : "f"(a[i]));

            unsigned long long b2[TN2];
#pragma unroll
            for (int j = 0; j < TN2; j += 2) {
                ulonglong2 t = *(const ulonglong2*)&Bs[buf][kk][tn0 + 2 * j];
                b2[j] = t.x; b2[j + 1] = t.y;
            }

#pragma unroll
            for (int i = 0; i < TM; i++)
#pragma unroll
                for (int j = 0; j < TN2; j++)
                    asm("fma.rn.f32x2 %0, %1, %2, %0;"
                        : "+l"(acc[i][j]) : "l"(a2[i]), "l"(b2[j]));
        }

        if (nxt) { storeA(buf ^ 1); storeB(buf ^ 1); }
        __syncthreads();
        buf ^= 1;
    }

#pragma unroll
    for (int i = 0; i < TM; i++) {
        float* crow = C + (size_t)(bm0 + tm0 + i) * N + bn0 + tn0;
#pragma unroll
        for (int j = 0; j < TN2; j += 2)
            *(ulonglong2*)(crow + 2 * j) = make_ulonglong2(acc[i][j], acc[i][j + 1]);
    }
}

// ---------------------------------------------------------------------------
// Windowed attention. One block per 4x4 guide tile: all 16 guide positions in
// tile (ty,tx) share window rows clip(ty-1..ty+1), cols clip(tx-1..tx+1).
// K/V 9x512 vectors staged in smem; 128 threads = 16 pos x 8 heads.
// ---------------------------------------------------------------------------
__global__ __launch_bounds__(128)
void attn_kernel(const float* __restrict__ Q, const float* __restrict__ Km,
                 const float* __restrict__ Vm, float* __restrict__ msg)
{
    __shared__ float Ks[9][512];
    __shared__ float Vs[9][512];

    const int tx = blockIdx.x;
    const int ty = blockIdx.y;
    const int tid = threadIdx.x;

    for (int idx = tid; idx < 9 * 128; idx += 128) {
        const int k  = idx >> 7;
        const int c4 = idx & 127;
        const int yy = min(max(ty - 1 + k / 3, 0), 31);
        const int xx = min(max(tx - 1 + k % 3, 0), 31);
        const int p  = yy * 32 + xx;
        ((float4*)&Ks[k][0])[c4] = ((const float4*)(Km + (size_t)p * 512))[c4];
        ((float4*)&Vs[k][0])[c4] = ((const float4*)(Vm + (size_t)p * 512))[c4];
    }
    __syncthreads();

    const int head = tid >> 4;
    const int pos  = tid & 15;
    const int n = (ty * 4 + (pos >> 2)) * 128 + tx * 4 + (pos & 3);

    const float4* q4 = (const float4*)(Q + (size_t)n * 512 + head * 64);

    float acc[9];
#pragma unroll
    for (int k = 0; k < 9; k++) acc[k] = 0.f;

#pragma unroll 4
    for (int e = 0; e < 16; e++) {
        float4 qv = q4[e];
#pragma unroll
        for (int k = 0; k < 9; k++) {
            float4 kv = ((const float4*)&Ks[k][head * 64])[e];
            acc[k] += qv.x * kv.x + qv.y * kv.y + qv.z * kv.z + qv.w * kv.w;
        }
    }

    float mx = acc[0];
#pragma unroll
    for (int k = 1; k < 9; k++) mx = fmaxf(mx, acc[k]);
    float s = 0.f;
#pragma unroll
    for (int k = 0; k < 9; k++) { acc[k] = __expf(0.125f * (acc[k] - mx)); s += acc[k]; }
    const float inv = 1.f / s;
#pragma unroll
    for (int k = 0; k < 9; k++) acc[k] *= inv;

    float4* out4 = (float4*)(msg + (size_t)n * 512 + head * 64);
#pragma unroll 4
    for (int e = 0; e < 16; e++) {
        float4 o = make_float4(0.f, 0.f, 0.f, 0.f);
#pragma unroll
        for (int k = 0; k < 9; k++) {
            float4 vv = ((const float4*)&Vs[k][head * 64])[e];
            o.x += acc[k] * vv.x;
            o.y += acc[k] * vv.y;
            o.z += acc[k] * vv.z;
            o.w += acc[k] * vv.w;
        }
        out4[e] = o;
    }
}

// ---------------------------------------------------------------------------
// LayerNorm over d=512 per position + transpose to channel-major output.
// ---------------------------------------------------------------------------
__global__ __launch_bounds__(256)
void ln_kernel(const float* __restrict__ X, const float* __restrict__ gamma,
               const float* __restrict__ beta, float* __restrict__ out)
{
    __shared__ float sm[16 * 513];

    const int nb   = blockIdx.x * 16;
    const int warp = threadIdx.x >> 5;
    const int lane = threadIdx.x & 31;

    for (int r = warp; r < 16; r += 8) {
        const int n = nb + r;
        const float* row = X + (size_t)n * 512;
        float v[16];
        float s = 0.f;
#pragma unroll
        for (int j = 0; j < 16; j++) { v[j] = row[lane + 32 * j]; s += v[j]; }
#pragma unroll
        for (int o = 16; o > 0; o >>= 1) s += __shfl_xor_sync(0xffffffffu, s, o);
        const float mu = s * (1.f / 512.f);
        float q = 0.f;
#pragma unroll
        for (int j = 0; j < 16; j++) { float d = v[j] - mu; q += d * d; }
#pragma unroll
        for (int o = 16; o > 0; o >>= 1) q += __shfl_xor_sync(0xffffffffu, q, o);
        const float rstd = rsqrtf(q * (1.f / 512.f) + 1e-5f);
#pragma unroll
        for (int j = 0; j < 16; j++) {
            const int o = lane + 32 * j;
            sm[r * 513 + o] = (v[j] - mu) * rstd * gamma[o] + beta[o];
        }
    }
    __syncthreads();

    const int i  = threadIdx.x & 15;
    const int ob = threadIdx.x >> 4;
    for (int o = ob; o < 512; o += 16)
        out[(size_t)o * 16384 + nb + i] = sm[i * 513 + o];
}

// ---------------------------------------------------------------------------
extern "C" void kernel_launch(void* const* d_in, const int* in_sizes, int n_in,
                              void* d_out, int out_size)
{
    const float* low   = (const float*)d_in[0];
    const float* guide = (const float*)d_in[1];
    const float* Wq    = (const float*)d_in[2];
    const float* Wk    = (const float*)d_in[3];
    const float* Wv    = (const float*)d_in[4];
    const float* Wm    = (const float*)d_in[5];
    const float* gamma = (const float*)d_in[6];
    const float* beta  = (const float*)d_in[7];
    float* out = (float*)d_out;

    float *Q, *K, *V, *M1, *M2;
    cudaGetSymbolAddress((void**)&Q,  g_Q);
    cudaGetSymbolAddress((void**)&K,  g_K);
    cudaGetSymbolAddress((void**)&V,  g_V);
    cudaGetSymbolAddress((void**)&M1, g_M1);
    cudaGetSymbolAddress((void**)&M2, g_M2);

    // Q = guide^T @ Wq^T   (A K-major): 128x128 tiles, grid 4x128
    sgemm2_kernel<1, 128, 128, 8, 16><<<dim3(4, 128, 1), 128>>>(
        guide, Wq, Wq, Q, Q, NPOS, DMODEL, DMODEL);
    // K,V = low^T @ {Wk,Wv}^T fused: 64x64 tiles, grid 8x16x2 = 256 blocks
    sgemm2_kernel<1, 64, 64, 4, 8><<<dim3(8, 16, 2), 128>>>(
        low, Wk, Wv, K, V, LPOS, DMODEL, DMODEL);
    // Windowed attention -> M1[n][d]
    attn_kernel<<<dim3(32, 32), 128>>>(Q, K, V, M1);
    // M2 = M1 @ Wm^T   (A M-major)
    sgemm2_kernel<0, 128, 128, 8, 16><<<dim3(4, 128, 1), 128>>>(
        M1, Wm, Wm, M2, M2, NPOS, DMODEL, DMODEL);
    // LayerNorm + transpose to channel-major output
    ln_kernel<<<1024, 256>>>(M2, gamma, beta, out);
}

// round 4
// speedup vs baseline: 2.7046x; 1.9813x over previous
#include <cuda_runtime.h>
#include <cuda_bf16.h>
#include <cstdint>

#define NPOS 16384   // 128*128 guide positions
#define LPOS 1024    // 32*32 low positions
#define DMODEL 512

// ---------------------------------------------------------------------------
// Scratch (static device globals — no allocation APIs allowed)
// ---------------------------------------------------------------------------
__device__ __nv_bfloat16 g_Ahi[NPOS * DMODEL];
__device__ __nv_bfloat16 g_Alo[NPOS * DMODEL];
__device__ __nv_bfloat16 g_Lhi[LPOS * DMODEL];
__device__ __nv_bfloat16 g_Llo[LPOS * DMODEL];
__device__ __nv_bfloat16 g_Whi[4 * DMODEL * DMODEL];
__device__ __nv_bfloat16 g_Wlo[4 * DMODEL * DMODEL];
__device__ float g_Q [NPOS * DMODEL];
__device__ float g_K [LPOS * DMODEL];
__device__ float g_V [LPOS * DMODEL];
__device__ float g_M1[NPOS * DMODEL];
__device__ float g_M2[NPOS * DMODEL];

// ---------------------------------------------------------------------------
// Baseline-PTX helpers (sm_80+ features only: work on plain sm_103 target)
// ---------------------------------------------------------------------------
__device__ __forceinline__ uint32_t smem_u32(const void* p) {
    uint32_t a;
    asm("{ .reg .u64 t; cvta.to.shared.u64 t, %1; cvt.u32.u64 %0, t; }" : "=r"(a) : "l"(p));
    return a;
}

#define CP16(dst, src) \
    asm volatile("cp.async.cg.shared.global [%0], [%1], 16;" :: "r"(dst), "l"(src))
#define CP_COMMIT() asm volatile("cp.async.commit_group;" ::: "memory")
#define CP_WAIT(n)  asm volatile("cp.async.wait_group %0;" :: "n"(n) : "memory")

#define LDSM4(r0, r1, r2, r3, addr) \
    asm volatile("ldmatrix.sync.aligned.m8n8.x4.shared.b16 {%0,%1,%2,%3}, [%4];" \
        : "=r"(r0), "=r"(r1), "=r"(r2), "=r"(r3) : "r"(addr))

#define MMA16816(d, a, b) \
    asm volatile("mma.sync.aligned.m16n8k16.row.col.f32.bf16.bf16.f32 " \
        "{%0,%1,%2,%3}, {%4,%5,%6,%7}, {%8,%9}, {%0,%1,%2,%3};" \
        : "+f"((d)[0]), "+f"((d)[1]), "+f"((d)[2]), "+f"((d)[3]) \
        : "r"((a)[0]), "r"((a)[1]), "r"((a)[2]), "r"((a)[3]), \
          "r"((b)[0]), "r"((b)[1]))

// ---------------------------------------------------------------------------
// mma_gemm: C[m][n] = sum_k A[m][k]*B[n][k], K=512 fixed, fp32 via bf16 hi/lo
// 3-term split (Ah*Bh + Ah*Bl + Al*Bh) on the tensor pipe (mma.sync bf16).
// CTA: 128x128 tile, 256 threads = 8 warps (4m x 2n), warp tile 32x64.
// K chunks of 32, double-buffered cp.async. smem rows 32 bf16 @ 80B pitch
// (64B data + 16B pad -> conflict-free ldmatrix, banks spread mod 32).
// Dual B/C via blockIdx.z.
// ---------------------------------------------------------------------------
#define PITCH 80
#define TILE_B (128 * PITCH)            // 10240 B per operand tile
#define STAGE_B (4 * TILE_B)            // Ahi,Alo,Bhi,Blo = 40960 B per stage

__global__ __launch_bounds__(256, 1)
void mma_gemm(const __nv_bfloat16* __restrict__ Ahi, const __nv_bfloat16* __restrict__ Alo,
              const __nv_bfloat16* __restrict__ Bhi0, const __nv_bfloat16* __restrict__ Blo0,
              float* __restrict__ C0,
              const __nv_bfloat16* __restrict__ Bhi1, const __nv_bfloat16* __restrict__ Blo1,
              float* __restrict__ C1)
{
    extern __shared__ char smem[];
    const uint32_t sb = smem_u32(smem);

    const __nv_bfloat16* Bhi = blockIdx.z ? Bhi1 : Bhi0;
    const __nv_bfloat16* Blo = blockIdx.z ? Blo1 : Blo0;
    float* C = blockIdx.z ? C1 : C0;

    const int tid  = threadIdx.x;
    const int wid  = tid >> 5;
    const int lane = tid & 31;
    const int bm0  = blockIdx.y * 128;
    const int bn0  = blockIdx.x * 128;
    const int wm   = (wid >> 1) * 32;    // warp m offset in tile
    const int wn   = (wid & 1) * 64;     // warp n offset in tile

    float acc[2][8][4];
#pragma unroll
    for (int i = 0; i < 2; i++)
#pragma unroll
        for (int j = 0; j < 8; j++)
#pragma unroll
            for (int r = 0; r < 4; r++) acc[i][j][r] = 0.f;

    // ---- async stage loader: 8 x 16B per thread per stage
    auto load_stage = [&](int s, int k0) {
        const uint32_t base = sb + s * STAGE_B;
#pragma unroll
        for (int i = 0; i < 2; i++) {
            const int idx = tid + 256 * i;        // 0..511
            const int row = idx >> 2;             // 0..127
            const int c   = idx & 3;              // 16B chunk in 64B row
            const uint32_t off = row * PITCH + c * 16;
            const size_t ga = ((size_t)(bm0 + row) * 512 + k0) * 2 + c * 16;
            const size_t gb = ((size_t)(bn0 + row) * 512 + k0) * 2 + c * 16;
            CP16(base + off,              (const char*)Ahi + ga);
            CP16(base + TILE_B + off,     (const char*)Alo + ga);
            CP16(base + 2 * TILE_B + off, (const char*)Bhi + gb);
            CP16(base + 3 * TILE_B + off, (const char*)Blo + gb);
        }
        CP_COMMIT();
    };

    // ---- compute one k32 chunk from stage s
    auto compute_stage = [&](int s) {
        const uint32_t base = sb + s * STAGE_B;
#pragma unroll
        for (int kk = 0; kk < 2; kk++) {          // two k16 halves
            const uint32_t koff = kk * 32;        // byte offset of k16 half

            uint32_t ah[2][4], al[2][4];
#pragma unroll
            for (int f = 0; f < 2; f++) {
                const uint32_t ra = base +
                    (uint32_t)(wm + f * 16 + (lane & 15)) * PITCH +
                    koff + ((lane >> 4) << 4);
                LDSM4(ah[f][0], ah[f][1], ah[f][2], ah[f][3], ra);
                LDSM4(al[f][0], al[f][1], al[f][2], al[f][3], ra + TILE_B);
            }

            uint32_t bh[8][2], bl[8][2];
#pragma unroll
            for (int g = 0; g < 4; g++) {
                const uint32_t rb = base + 2 * TILE_B +
                    (uint32_t)(wn + g * 16 + (lane & 7) + ((lane >> 4) << 3)) * PITCH +
                    koff + (((lane >> 3) & 1) << 4);
                LDSM4(bh[2*g][0], bh[2*g][1], bh[2*g+1][0], bh[2*g+1][1], rb);
                LDSM4(bl[2*g][0], bl[2*g][1], bl[2*g+1][0], bl[2*g+1][1], rb + TILE_B);
            }

#pragma unroll
            for (int f = 0; f < 2; f++)
#pragma unroll
                for (int g = 0; g < 8; g++) {
                    MMA16816(acc[f][g], ah[f], bh[g]);
                    MMA16816(acc[f][g], ah[f], bl[g]);
                    MMA16816(acc[f][g], al[f], bh[g]);
                }
        }
    };

    load_stage(0, 0);
    load_stage(1, 32);

#pragma unroll
    for (int c = 0; c < 16; c++) {
        if (c < 14) { CP_WAIT(1); } else { CP_WAIT(0); }
        __syncthreads();
        compute_stage(c & 1);
        if (c + 2 < 16) {
            __syncthreads();
            load_stage(c & 1, (c + 2) * 32);
        }
    }

    // ---- epilogue: acc -> C (fp32, row stride 512)
    const int qrow = lane >> 2;          // 0..7
    const int qcol = (lane & 3) * 2;     // 0,2,4,6
#pragma unroll
    for (int f = 0; f < 2; f++)
#pragma unroll
        for (int g = 0; g < 8; g++) {
            const int row = bm0 + wm + f * 16 + qrow;
            const int col = bn0 + wn + g * 8 + qcol;
            *(float2*)(C + (size_t)row * 512 + col) =
                make_float2(acc[f][g][0], acc[f][g][1]);
            *(float2*)(C + (size_t)(row + 8) * 512 + col) =
                make_float2(acc[f][g][2], acc[f][g][3]);
        }
}

// ---------------------------------------------------------------------------
// convT: in fp32 [512][M] (channel-major) -> hi/lo bf16 [M][512] (transpose).
// ---------------------------------------------------------------------------
__global__ __launch_bounds__(256)
void convT_kernel(const float* __restrict__ in, __nv_bfloat16* __restrict__ hi,
                  __nv_bfloat16* __restrict__ lo, int M)
{
    __shared__ float t[32][33];
    const int tx = threadIdx.x, ty = threadIdx.y;
    const int mb = blockIdx.x * 32, kb = blockIdx.y * 32;
#pragma unroll
    for (int j = 0; j < 4; j++)
        t[ty + 8 * j][tx] = in[(size_t)(kb + ty + 8 * j) * M + mb + tx];
    __syncthreads();
#pragma unroll
    for (int j = 0; j < 4; j++) {
        const float v = t[tx][ty + 8 * j];
        const __nv_bfloat16 h = __float2bfloat16(v);
        const __nv_bfloat16 l = __float2bfloat16(v - __bfloat162float(h));
        const size_t o = (size_t)(mb + ty + 8 * j) * 512 + kb + tx;
        hi[o] = h; lo[o] = l;
    }
}

// ---------------------------------------------------------------------------
// conv_elem: elementwise fp32 -> bf16 hi/lo (layout-preserving), n4 float4s.
// ---------------------------------------------------------------------------
__global__ __launch_bounds__(256)
void conv_elem_kernel(const float4* __restrict__ in, ushort4* __restrict__ hi,
                      ushort4* __restrict__ lo, int n4)
{
    const int i = blockIdx.x * 256 + threadIdx.x;
    if (i >= n4) return;
    const float4 v = in[i];
    ushort4 h, l;
    __nv_bfloat16 b;
    b = __float2bfloat16(v.x); h.x = __bfloat16_as_ushort(b);
    l.x = __bfloat16_as_ushort(__float2bfloat16(v.x - __bfloat162float(b)));
    b = __float2bfloat16(v.y); h.y = __bfloat16_as_ushort(b);
    l.y = __bfloat16_as_ushort(__float2bfloat16(v.y - __bfloat162float(b)));
    b = __float2bfloat16(v.z); h.z = __bfloat16_as_ushort(b);
    l.z = __bfloat16_as_ushort(__float2bfloat16(v.z - __bfloat162float(b)));
    b = __float2bfloat16(v.w); h.w = __bfloat16_as_ushort(b);
    l.w = __bfloat16_as_ushort(__float2bfloat16(v.w - __bfloat162float(b)));
    hi[i] = h; lo[i] = l;
}

// ---------------------------------------------------------------------------
// Windowed attention. One block per 4x4 guide tile (shared 3x3 window).
// ---------------------------------------------------------------------------
__global__ __launch_bounds__(128)
void attn_kernel(const float* __restrict__ Q, const float* __restrict__ Km,
                 const float* __restrict__ Vm, float* __restrict__ msg)
{
    __shared__ float Ks[9][512];
    __shared__ float Vs[9][512];

    const int tx = blockIdx.x;
    const int ty = blockIdx.y;
    const int tid = threadIdx.x;

    for (int idx = tid; idx < 9 * 128; idx += 128) {
        const int k  = idx >> 7;
        const int c4 = idx & 127;
        const int yy = min(max(ty - 1 + k / 3, 0), 31);
        const int xx = min(max(tx - 1 + k % 3, 0), 31);
        const int p  = yy * 32 + xx;
        ((float4*)&Ks[k][0])[c4] = ((const float4*)(Km + (size_t)p * 512))[c4];
        ((float4*)&Vs[k][0])[c4] = ((const float4*)(Vm + (size_t)p * 512))[c4];
    }
    __syncthreads();

    const int head = tid >> 4;
    const int pos  = tid & 15;
    const int n = (ty * 4 + (pos >> 2)) * 128 + tx * 4 + (pos & 3);

    const float4* q4 = (const float4*)(Q + (size_t)n * 512 + head * 64);

    float acc[9];
#pragma unroll
    for (int k = 0; k < 9; k++) acc[k] = 0.f;

#pragma unroll 4
    for (int e = 0; e < 16; e++) {
        float4 qv = q4[e];
#pragma unroll
        for (int k = 0; k < 9; k++) {
            float4 kv = ((const float4*)&Ks[k][head * 64])[e];
            acc[k] += qv.x * kv.x + qv.y * kv.y + qv.z * kv.z + qv.w * kv.w;
        }
    }

    float mx = acc[0];
#pragma unroll
    for (int k = 1; k < 9; k++) mx = fmaxf(mx, acc[k]);
    float s = 0.f;
#pragma unroll
    for (int k = 0; k < 9; k++) { acc[k] = __expf(0.125f * (acc[k] - mx)); s += acc[k]; }
    const float inv = 1.f / s;
#pragma unroll
    for (int k = 0; k < 9; k++) acc[k] *= inv;

    float4* out4 = (float4*)(msg + (size_t)n * 512 + head * 64);
#pragma unroll 4
    for (int e = 0; e < 16; e++) {
        float4 o = make_float4(0.f, 0.f, 0.f, 0.f);
#pragma unroll
        for (int k = 0; k < 9; k++) {
            float4 vv = ((const float4*)&Vs[k][head * 64])[e];
            o.x += acc[k] * vv.x;
            o.y += acc[k] * vv.y;
            o.z += acc[k] * vv.z;
            o.w += acc[k] * vv.w;
        }
        out4[e] = o;
    }
}

// ---------------------------------------------------------------------------
// LayerNorm over d=512 per position + transpose to channel-major output.
// ---------------------------------------------------------------------------
__global__ __launch_bounds__(256)
void ln_kernel(const float* __restrict__ X, const float* __restrict__ gamma,
               const float* __restrict__ beta, float* __restrict__ out)
{
    __shared__ float sm[16 * 513];

    const int nb   = blockIdx.x * 16;
    const int warp = threadIdx.x >> 5;
    const int lane = threadIdx.x & 31;

    for (int r = warp; r < 16; r += 8) {
        const int n = nb + r;
        const float* row = X + (size_t)n * 512;
        float v[16];
        float s = 0.f;
#pragma unroll
        for (int j = 0; j < 16; j++) { v[j] = row[lane + 32 * j]; s += v[j]; }
#pragma unroll
        for (int o = 16; o > 0; o >>= 1) s += __shfl_xor_sync(0xffffffffu, s, o);
        const float mu = s * (1.f / 512.f);
        float q = 0.f;
#pragma unroll
        for (int j = 0; j < 16; j++) { float d = v[j] - mu; q += d * d; }
#pragma unroll
        for (int o = 16; o > 0; o >>= 1) q += __shfl_xor_sync(0xffffffffu, q, o);
        const float rstd = rsqrtf(q * (1.f / 512.f) + 1e-5f);
#pragma unroll
        for (int j = 0; j < 16; j++) {
            const int o = lane + 32 * j;
            sm[r * 513 + o] = (v[j] - mu) * rstd * gamma[o] + beta[o];
        }
    }
    __syncthreads();

    const int i  = threadIdx.x & 15;
    const int ob = threadIdx.x >> 4;
    for (int o = ob; o < 512; o += 16)
        out[(size_t)o * 16384 + nb + i] = sm[i * 513 + o];
}

// ---------------------------------------------------------------------------
extern "C" void kernel_launch(void* const* d_in, const int* in_sizes, int n_in,
                              void* d_out, int out_size)
{
    const float* low   = (const float*)d_in[0];
    const float* guide = (const float*)d_in[1];
    const float* Wq    = (const float*)d_in[2];
    const float* Wk    = (const float*)d_in[3];
    const float* Wv    = (const float*)d_in[4];
    const float* Wm    = (const float*)d_in[5];
    const float* gamma = (const float*)d_in[6];
    const float* beta  = (const float*)d_in[7];
    float* out = (float*)d_out;

    __nv_bfloat16 *Ahi, *Alo, *Lhi, *Llo, *Whi, *Wlo;
    float *Q, *K, *V, *M1, *M2;
    cudaGetSymbolAddress((void**)&Ahi, g_Ahi);
    cudaGetSymbolAddress((void**)&Alo, g_Alo);
    cudaGetSymbolAddress((void**)&Lhi, g_Lhi);
    cudaGetSymbolAddress((void**)&Llo, g_Llo);
    cudaGetSymbolAddress((void**)&Whi, g_Whi);
    cudaGetSymbolAddress((void**)&Wlo, g_Wlo);
    cudaGetSymbolAddress((void**)&Q,  g_Q);
    cudaGetSymbolAddress((void**)&K,  g_K);
    cudaGetSymbolAddress((void**)&V,  g_V);
    cudaGetSymbolAddress((void**)&M1, g_M1);
    cudaGetSymbolAddress((void**)&M2, g_M2);

    const int W_ELEMS = DMODEL * DMODEL;       // 262144
    const int GEMM_SMEM = 2 * STAGE_B;         // 81920 B

    cudaFuncSetAttribute(mma_gemm, cudaFuncAttributeMaxDynamicSharedMemorySize,
                         GEMM_SMEM);

    // Convert + transpose inputs (channel-major -> row-major bf16 hi/lo)
    convT_kernel<<<dim3(NPOS / 32, 16), dim3(32, 8)>>>(guide, Ahi, Alo, NPOS);
    convT_kernel<<<dim3(LPOS / 32, 16), dim3(32, 8)>>>(low, Lhi, Llo, LPOS);

    // Convert weights (elementwise): slots 0=Wq, 1=Wk, 2=Wv, 3=Wm
    conv_elem_kernel<<<W_ELEMS / 4 / 256, 256>>>(
        (const float4*)Wq, (ushort4*)(Whi + 0 * W_ELEMS), (ushort4*)(Wlo + 0 * W_ELEMS), W_ELEMS / 4);
    conv_elem_kernel<<<W_ELEMS / 4 / 256, 256>>>(
        (const float4*)Wk, (ushort4*)(Whi + 1 * W_ELEMS), (ushort4*)(Wlo + 1 * W_ELEMS), W_ELEMS / 4);
    conv_elem_kernel<<<W_ELEMS / 4 / 256, 256>>>(
        (const float4*)Wv, (ushort4*)(Whi + 2 * W_ELEMS), (ushort4*)(Wlo + 2 * W_ELEMS), W_ELEMS / 4);
    conv_elem_kernel<<<W_ELEMS / 4 / 256, 256>>>(
        (const float4*)Wm, (ushort4*)(Whi + 3 * W_ELEMS), (ushort4*)(Wlo + 3 * W_ELEMS), W_ELEMS / 4);

    // Q = guide @ Wq^T : grid (N/128=4, M/128=128)
    mma_gemm<<<dim3(4, 128, 1), 256, GEMM_SMEM>>>(
        Ahi, Alo, Whi, Wlo, Q, Whi, Wlo, Q);
    // K,V = low @ {Wk,Wv}^T fused via z: grid (4, 8, 2)
    mma_gemm<<<dim3(4, 8, 2), 256, GEMM_SMEM>>>(
        Lhi, Llo,
        Whi + 1 * W_ELEMS, Wlo + 1 * W_ELEMS, K,
        Whi + 2 * W_ELEMS, Wlo + 2 * W_ELEMS, V);

    // Windowed attention -> M1[n][d] (fp32)
    attn_kernel<<<dim3(32, 32), 128>>>(Q, K, V, M1);

    // Convert M1 (row-major, elementwise) into A buffers
    conv_elem_kernel<<<(NPOS * DMODEL / 4 + 255) / 256, 256>>>(
        (const float4*)M1, (ushort4*)Ahi, (ushort4*)Alo, NPOS * DMODEL / 4);

    // M2 = M1 @ Wm^T
    mma_gemm<<<dim3(4, 128, 1), 256, GEMM_SMEM>>>(
        Ahi, Alo, Whi + 3 * W_ELEMS, Wlo + 3 * W_ELEMS, M2,
        Whi + 3 * W_ELEMS, Wlo + 3 * W_ELEMS, M2);

    // LayerNorm + transpose to channel-major output
    ln_kernel<<<1024, 256>>>(M2, gamma, beta, out);
}

// round 5
// speedup vs baseline: 3.7423x; 1.3837x over previous
#include <cuda_runtime.h>
#include <cuda_fp16.h>
#include <cstdint>

#define NPOS 16384   // 128*128 guide positions
#define LPOS 1024    // 32*32 low positions
#define DMODEL 512

// ---------------------------------------------------------------------------
// Scratch (static device globals — no allocation APIs allowed)
// ---------------------------------------------------------------------------
__device__ __half g_Af [NPOS * DMODEL];          // fp16 activations (guide, then M1)
__device__ __half g_Lf [LPOS * DMODEL];          // fp16 low activations
__device__ __half g_Whi[4 * DMODEL * DMODEL];    // weight hi (fp16)
__device__ __half g_Wlo[4 * DMODEL * DMODEL];    // weight lo (fp16 residual)
__device__ float g_Q [NPOS * DMODEL];
__device__ float g_K [LPOS * DMODEL];
__device__ float g_V [LPOS * DMODEL];
__device__ float g_M2[NPOS * DMODEL];

// ---------------------------------------------------------------------------
// Baseline-PTX helpers (sm_80+ features only: work on plain sm_103 target)
// ---------------------------------------------------------------------------
__device__ __forceinline__ uint32_t smem_u32(const void* p) {
    uint32_t a;
    asm("{ .reg .u64 t; cvta.to.shared.u64 t, %1; cvt.u32.u64 %0, t; }" : "=r"(a) : "l"(p));
    return a;
}

#define CP16(dst, src) \
    asm volatile("cp.async.cg.shared.global [%0], [%1], 16;" :: "r"(dst), "l"(src))
#define CP_COMMIT() asm volatile("cp.async.commit_group;" ::: "memory")
#define CP_WAIT(n)  asm volatile("cp.async.wait_group %0;" :: "n"(n) : "memory")

#define LDSM4(r0, r1, r2, r3, addr) \
    asm volatile("ldmatrix.sync.aligned.m8n8.x4.shared.b16 {%0,%1,%2,%3}, [%4];" \
        : "=r"(r0), "=r"(r1), "=r"(r2), "=r"(r3) : "r"(addr))

#define MMA16816F(d, a, b) \
    asm volatile("mma.sync.aligned.m16n8k16.row.col.f32.f16.f16.f32 " \
        "{%0,%1,%2,%3}, {%4,%5,%6,%7}, {%8,%9}, {%0,%1,%2,%3};" \
        : "+f"((d)[0]), "+f"((d)[1]), "+f"((d)[2]), "+f"((d)[3]) \
        : "r"((a)[0]), "r"((a)[1]), "r"((a)[2]), "r"((a)[3]), \
          "r"((b)[0]), "r"((b)[1]))

// ---------------------------------------------------------------------------
// mma_gemm: C[m][n] = sum_k A[m][k]*B[n][k], K=512 fixed.
// fp32 emulation: A single fp16 (round), B = Bhi + Blo fp16 split (exact):
//   C = A*Bhi + A*Blo, fp32 accumulate (2 MMAs per k16 instead of 3).
// CTA: 128x128 tile, 256 threads = 8 warps (4m x 2n), warp tile 32x64.
// K chunks of 32, triple-buffered cp.async. smem rows 32 fp16 @ 80B pitch.
// Dual B/C via blockIdx.z.
// ---------------------------------------------------------------------------
#define PITCH 80
#define TILE_B (128 * PITCH)            // 10240 B per operand tile
#define STAGE_B (3 * TILE_B)            // A, Bhi, Blo = 30720 B per stage
#define NSTAGE 3

__global__ __launch_bounds__(256, 1)
void mma_gemm(const __half* __restrict__ A,
              const __half* __restrict__ Bhi0, const __half* __restrict__ Blo0,
              float* __restrict__ C0,
              const __half* __restrict__ Bhi1, const __half* __restrict__ Blo1,
              float* __restrict__ C1)
{
    extern __shared__ char smem[];
    const uint32_t sb = smem_u32(smem);

    const __half* Bhi = blockIdx.z ? Bhi1 : Bhi0;
    const __half* Blo = blockIdx.z ? Blo1 : Blo0;
    float* C = blockIdx.z ? C1 : C0;

    const int tid  = threadIdx.x;
    const int wid  = tid >> 5;
    const int lane = tid & 31;
    const int bm0  = blockIdx.y * 128;
    const int bn0  = blockIdx.x * 128;
    const int wm   = (wid >> 1) * 32;    // warp m offset in tile
    const int wn   = (wid & 1) * 64;     // warp n offset in tile

    float acc[2][8][4];
#pragma unroll
    for (int i = 0; i < 2; i++)
#pragma unroll
        for (int j = 0; j < 8; j++)
#pragma unroll
            for (int r = 0; r < 4; r++) acc[i][j][r] = 0.f;

    // ---- async stage loader: 6 x 16B per thread per stage
    auto load_stage = [&](int s, int k0) {
        const uint32_t base = sb + s * STAGE_B;
#pragma unroll
        for (int i = 0; i < 2; i++) {
            const int idx = tid + 256 * i;        // 0..511
            const int row = idx >> 2;             // 0..127
            const int c   = idx & 3;              // 16B chunk in 64B row
            const uint32_t off = row * PITCH + c * 16;
            const size_t ga = ((size_t)(bm0 + row) * 512 + k0) * 2 + c * 16;
            const size_t gb = ((size_t)(bn0 + row) * 512 + k0) * 2 + c * 16;
            CP16(base + off,              (const char*)A   + ga);
            CP16(base + TILE_B + off,     (const char*)Bhi + gb);
            CP16(base + 2 * TILE_B + off, (const char*)Blo + gb);
        }
        CP_COMMIT();
    };

    // ---- compute one k32 chunk from stage s
    auto compute_stage = [&](int s) {
        const uint32_t base = sb + s * STAGE_B;
#pragma unroll
        for (int kk = 0; kk < 2; kk++) {          // two k16 halves
            const uint32_t koff = kk * 32;        // byte offset of k16 half

            uint32_t a[2][4];
#pragma unroll
            for (int f = 0; f < 2; f++) {
                const uint32_t ra = base +
                    (uint32_t)(wm + f * 16 + (lane & 15)) * PITCH +
                    koff + ((lane >> 4) << 4);
                LDSM4(a[f][0], a[f][1], a[f][2], a[f][3], ra);
            }

            uint32_t bh[8][2], bl[8][2];
#pragma unroll
            for (int g = 0; g < 4; g++) {
                const uint32_t rb = base + TILE_B +
                    (uint32_t)(wn + g * 16 + (lane & 7) + ((lane >> 4) << 3)) * PITCH +
                    koff + (((lane >> 3) & 1) << 4);
                LDSM4(bh[2*g][0], bh[2*g][1], bh[2*g+1][0], bh[2*g+1][1], rb);
                LDSM4(bl[2*g][0], bl[2*g][1], bl[2*g+1][0], bl[2*g+1][1], rb + TILE_B);
            }

#pragma unroll
            for (int f = 0; f < 2; f++)
#pragma unroll
                for (int g = 0; g < 8; g++) {
                    MMA16816F(acc[f][g], a[f], bh[g]);
                    MMA16816F(acc[f][g], a[f], bl[g]);
                }
        }
    };

    load_stage(0, 0);
    load_stage(1, 32);
    load_stage(2, 64);

#pragma unroll
    for (int c = 0; c < 16; c++) {
        if (c <= 13)      { CP_WAIT(2); }
        else if (c == 14) { CP_WAIT(1); }
        else              { CP_WAIT(0); }
        __syncthreads();
        compute_stage(c % NSTAGE);
        if (c + NSTAGE < 16) {
            __syncthreads();
            load_stage(c % NSTAGE, (c + NSTAGE) * 32);
        }
    }

    // ---- epilogue: acc -> C (fp32, row stride 512)
    const int qrow = lane >> 2;          // 0..7
    const int qcol = (lane & 3) * 2;     // 0,2,4,6
#pragma unroll
    for (int f = 0; f < 2; f++)
#pragma unroll
        for (int g = 0; g < 8; g++) {
            const int row = bm0 + wm + f * 16 + qrow;
            const int col = bn0 + wn + g * 8 + qcol;
            *(float2*)(C + (size_t)row * 512 + col) =
                make_float2(acc[f][g][0], acc[f][g][1]);
            *(float2*)(C + (size_t)(row + 8) * 512 + col) =
                make_float2(acc[f][g][2], acc[f][g][3]);
        }
}

// ---------------------------------------------------------------------------
// convT: in fp32 [512][M] (channel-major) -> fp16 [M][512] (transpose+round).
// ---------------------------------------------------------------------------
__global__ __launch_bounds__(256)
void convT_kernel(const float* __restrict__ in, __half* __restrict__ outp, int M)
{
    __shared__ float t[32][33];
    const int tx = threadIdx.x, ty = threadIdx.y;
    const int mb = blockIdx.x * 32, kb = blockIdx.y * 32;
#pragma unroll
    for (int j = 0; j < 4; j++)
        t[ty + 8 * j][tx] = in[(size_t)(kb + ty + 8 * j) * M + mb + tx];
    __syncthreads();
#pragma unroll
    for (int j = 0; j < 4; j++) {
        const float v = t[tx][ty + 8 * j];
        outp[(size_t)(mb + ty + 8 * j) * 512 + kb + tx] = __float2half(v);
    }
}

// ---------------------------------------------------------------------------
// conv_w: all 4 weights in one launch (blockIdx.z selects). fp32 -> hi/lo fp16.
// ---------------------------------------------------------------------------
__global__ __launch_bounds__(256)
void conv_w_kernel(const float4* __restrict__ w0, const float4* __restrict__ w1,
                   const float4* __restrict__ w2, const float4* __restrict__ w3,
                   __half* __restrict__ whi, __half* __restrict__ wlo)
{
    const int z = blockIdx.z;
    const float4* src = (z == 0) ? w0 : (z == 1) ? w1 : (z == 2) ? w2 : w3;
    const int i = blockIdx.x * 256 + threadIdx.x;        // 0..65535
    const float4 v = src[i];

    const __half hx = __float2half(v.x), hy = __float2half(v.y);
    const __half hz = __float2half(v.z), hw = __float2half(v.w);
    const __half lx = __float2half(v.x - __half2float(hx));
    const __half ly = __float2half(v.y - __half2float(hy));
    const __half lz = __float2half(v.z - __half2float(hz));
    const __half lw = __float2half(v.w - __half2float(hw));

    const size_t o = (size_t)z * (DMODEL * DMODEL / 4) + i;
    ((ushort4*)whi)[o] = make_ushort4(__half_as_ushort(hx), __half_as_ushort(hy),
                                      __half_as_ushort(hz), __half_as_ushort(hw));
    ((ushort4*)wlo)[o] = make_ushort4(__half_as_ushort(lx), __half_as_ushort(ly),
                                      __half_as_ushort(lz), __half_as_ushort(lw));
}

// ---------------------------------------------------------------------------
// Windowed attention. One block per 4x4 guide tile (shared 3x3 window).
// Epilogue writes fp16 directly (input to the Wm GEMM).
// ---------------------------------------------------------------------------
__global__ __launch_bounds__(128)
void attn_kernel(const float* __restrict__ Q, const float* __restrict__ Km,
                 const float* __restrict__ Vm, __half* __restrict__ msg)
{
    __shared__ float Ks[9][512];
    __shared__ float Vs[9][512];

    const int tx = blockIdx.x;
    const int ty = blockIdx.y;
    const int tid = threadIdx.x;

    for (int idx = tid; idx < 9 * 128; idx += 128) {
        const int k  = idx >> 7;
        const int c4 = idx & 127;
        const int yy = min(max(ty - 1 + k / 3, 0), 31);
        const int xx = min(max(tx - 1 + k % 3, 0), 31);
        const int p  = yy * 32 + xx;
        ((float4*)&Ks[k][0])[c4] = ((const float4*)(Km + (size_t)p * 512))[c4];
        ((float4*)&Vs[k][0])[c4] = ((const float4*)(Vm + (size_t)p * 512))[c4];
    }
    __syncthreads();

    const int head = tid >> 4;
    const int pos  = tid & 15;
    const int n = (ty * 4 + (pos >> 2)) * 128 + tx * 4 + (pos & 3);

    const float4* q4 = (const float4*)(Q + (size_t)n * 512 + head * 64);

    float acc[9];
#pragma unroll
    for (int k = 0; k < 9; k++) acc[k] = 0.f;

#pragma unroll 4
    for (int e = 0; e < 16; e++) {
        float4 qv = q4[e];
#pragma unroll
        for (int k = 0; k < 9; k++) {
            float4 kv = ((const float4*)&Ks[k][head * 64])[e];
            acc[k] += qv.x * kv.x + qv.y * kv.y + qv.z * kv.z + qv.w * kv.w;
        }
    }

    float mx = acc[0];
#pragma unroll
    for (int k = 1; k < 9; k++) mx = fmaxf(mx, acc[k]);
    float s = 0.f;
#pragma unroll
    for (int k = 0; k < 9; k++) { acc[k] = __expf(0.125f * (acc[k] - mx)); s += acc[k]; }
    const float inv = 1.f / s;
#pragma unroll
    for (int k = 0; k < 9; k++) acc[k] *= inv;

    __half* outp = msg + (size_t)n * 512 + head * 64;
#pragma unroll 4
    for (int e = 0; e < 16; e++) {
        float4 o = make_float4(0.f, 0.f, 0.f, 0.f);
#pragma unroll
        for (int k = 0; k < 9; k++) {
            float4 vv = ((const float4*)&Vs[k][head * 64])[e];
            o.x += acc[k] * vv.x;
            o.y += acc[k] * vv.y;
            o.z += acc[k] * vv.z;
            o.w += acc[k] * vv.w;
        }
        const __half2 h0 = __floats2half2_rn(o.x, o.y);
        const __half2 h1 = __floats2half2_rn(o.z, o.w);
        uint2 pk;
        pk.x = *(const uint32_t*)&h0;
        pk.y = *(const uint32_t*)&h1;
        *(uint2*)(outp + e * 4) = pk;
    }
}

// ---------------------------------------------------------------------------
// LayerNorm over d=512 per position + transpose to channel-major output.
// ---------------------------------------------------------------------------
__global__ __launch_bounds__(256)
void ln_kernel(const float* __restrict__ X, const float* __restrict__ gamma,
               const float* __restrict__ beta, float* __restrict__ out)
{
    __shared__ float sm[16 * 513];

    const int nb   = blockIdx.x * 16;
    const int warp = threadIdx.x >> 5;
    const int lane = threadIdx.x & 31;

    for (int r = warp; r < 16; r += 8) {
        const int n = nb + r;
        const float* row = X + (size_t)n * 512;
        float v[16];
        float s = 0.f;
#pragma unroll
        for (int j = 0; j < 16; j++) { v[j] = row[lane + 32 * j]; s += v[j]; }
#pragma unroll
        for (int o = 16; o > 0; o >>= 1) s += __shfl_xor_sync(0xffffffffu, s, o);
        const float mu = s * (1.f / 512.f);
        float q = 0.f;
#pragma unroll
        for (int j = 0; j < 16; j++) { float d = v[j] - mu; q += d * d; }
#pragma unroll
        for (int o = 16; o > 0; o >>= 1) q += __shfl_xor_sync(0xffffffffu, q, o);
        const float rstd = rsqrtf(q * (1.f / 512.f) + 1e-5f);
#pragma unroll
        for (int j = 0; j < 16; j++) {
            const int o = lane + 32 * j;
            sm[r * 513 + o] = (v[j] - mu) * rstd * gamma[o] + beta[o];
        }
    }
    __syncthreads();

    const int i  = threadIdx.x & 15;
    const int ob = threadIdx.x >> 4;
    for (int o = ob; o < 512; o += 16)
        out[(size_t)o * 16384 + nb + i] = sm[i * 513 + o];
}

// ---------------------------------------------------------------------------
extern "C" void kernel_launch(void* const* d_in, const int* in_sizes, int n_in,
                              void* d_out, int out_size)
{
    const float* low   = (const float*)d_in[0];
    const float* guide = (const float*)d_in[1];
    const float* Wq    = (const float*)d_in[2];
    const float* Wk    = (const float*)d_in[3];
    const float* Wv    = (const float*)d_in[4];
    const float* Wm    = (const float*)d_in[5];
    const float* gamma = (const float*)d_in[6];
    const float* beta  = (const float*)d_in[7];
    float* out = (float*)d_out;

    __half *Af, *Lf, *Whi, *Wlo;
    float *Q, *K, *V, *M2;
    cudaGetSymbolAddress((void**)&Af,  g_Af);
    cudaGetSymbolAddress((void**)&Lf,  g_Lf);
    cudaGetSymbolAddress((void**)&Whi, g_Whi);
    cudaGetSymbolAddress((void**)&Wlo, g_Wlo);
    cudaGetSymbolAddress((void**)&Q,   g_Q);
    cudaGetSymbolAddress((void**)&K,   g_K);
    cudaGetSymbolAddress((void**)&V,   g_V);
    cudaGetSymbolAddress((void**)&M2,  g_M2);

    const int W_ELEMS = DMODEL * DMODEL;       // 262144
    const int GEMM_SMEM = NSTAGE * STAGE_B;    // 92160 B

    cudaFuncSetAttribute(mma_gemm, cudaFuncAttributeMaxDynamicSharedMemorySize,
                         GEMM_SMEM);

    // Convert + transpose activations (channel-major fp32 -> row-major fp16)
    convT_kernel<<<dim3(NPOS / 32, 16), dim3(32, 8)>>>(guide, Af, NPOS);
    convT_kernel<<<dim3(LPOS / 32, 16), dim3(32, 8)>>>(low, Lf, LPOS);

    // Convert all 4 weights in one launch: slots 0=Wq, 1=Wk, 2=Wv, 3=Wm
    conv_w_kernel<<<dim3(W_ELEMS / 4 / 256, 1, 4), 256>>>(
        (const float4*)Wq, (const float4*)Wk, (const float4*)Wv, (const float4*)Wm,
        Whi, Wlo);

    // Q = guide @ Wq^T : grid (N/128=4, M/128=128)
    mma_gemm<<<dim3(4, 128, 1), 256, GEMM_SMEM>>>(
        Af, Whi, Wlo, Q, Whi, Wlo, Q);
    // K,V = low @ {Wk,Wv}^T fused via z: grid (4, 8, 2)
    mma_gemm<<<dim3(4, 8, 2), 256, GEMM_SMEM>>>(
        Lf,
        Whi + 1 * W_ELEMS, Wlo + 1 * W_ELEMS, K,
        Whi + 2 * W_ELEMS, Wlo + 2 * W_ELEMS, V);

    // Windowed attention -> fp16 msg directly into Af (guide no longer needed)
    attn_kernel<<<dim3(32, 32), 128>>>(Q, K, V, Af);

    // M2 = msg @ Wm^T
    mma_gemm<<<dim3(4, 128, 1), 256, GEMM_SMEM>>>(
        Af, Whi + 3 * W_ELEMS, Wlo + 3 * W_ELEMS, M2,
        Whi + 3 * W_ELEMS, Wlo + 3 * W_ELEMS, M2);

    // LayerNorm + transpose to channel-major output
    ln_kernel<<<1024, 256>>>(M2, gamma, beta, out);
}

// round 6
// speedup vs baseline: 3.9116x; 1.0452x over previous
#include <cuda_runtime.h>
#include <cuda_fp16.h>
#include <cstdint>

#define NPOS 16384   // 128*128 guide positions
#define LPOS 1024    // 32*32 low positions
#define DMODEL 512

// ---------------------------------------------------------------------------
// Scratch (static device globals — no allocation APIs allowed)
// ---------------------------------------------------------------------------
__device__ __half g_Af [NPOS * DMODEL];          // fp16 activations (guide, then msg)
__device__ __half g_Lf [LPOS * DMODEL];          // fp16 low activations
__device__ __half g_Whi[4 * DMODEL * DMODEL];    // weight hi (fp16)
__device__ __half g_Wlo[4 * DMODEL * DMODEL];    // weight lo (fp16 residual)
__device__ float g_Q [NPOS * DMODEL];
__device__ float g_K [LPOS * DMODEL];
__device__ float g_V [LPOS * DMODEL];
__device__ float g_M2[NPOS * DMODEL];

// ---------------------------------------------------------------------------
// Baseline-PTX helpers (sm_80+ features only: work on plain sm_103 target)
// ---------------------------------------------------------------------------
__device__ __forceinline__ uint32_t smem_u32(const void* p) {
    uint32_t a;
    asm("{ .reg .u64 t; cvta.to.shared.u64 t, %1; cvt.u32.u64 %0, t; }" : "=r"(a) : "l"(p));
    return a;
}

#define CP16(dst, src) \
    asm volatile("cp.async.cg.shared.global [%0], [%1], 16;" :: "r"(dst), "l"(src))
#define CP_COMMIT() asm volatile("cp.async.commit_group;" ::: "memory")
#define CP_WAIT(n)  asm volatile("cp.async.wait_group %0;" :: "n"(n) : "memory")

#define LDSM4(r0, r1, r2, r3, addr) \
    asm volatile("ldmatrix.sync.aligned.m8n8.x4.shared.b16 {%0,%1,%2,%3}, [%4];" \
        : "=r"(r0), "=r"(r1), "=r"(r2), "=r"(r3) : "r"(addr))

#define MMA16816F(d, a, b) \
    asm volatile("mma.sync.aligned.m16n8k16.row.col.f32.f16.f16.f32 " \
        "{%0,%1,%2,%3}, {%4,%5,%6,%7}, {%8,%9}, {%0,%1,%2,%3};" \
        : "+f"((d)[0]), "+f"((d)[1]), "+f"((d)[2]), "+f"((d)[3]) \
        : "r"((a)[0]), "r"((a)[1]), "r"((a)[2]), "r"((a)[3]), \
          "r"((b)[0]), "r"((b)[1]))

// ---------------------------------------------------------------------------
// mma_gemm: C[m][n] = sum_k A[m][k]*B[n][k], K=512 fixed.
// fp32 emulation: A rounded to fp16, B = Bhi + Blo fp16 split (exact):
//   C = A*Bhi + A*Blo, fp32 accumulate.
// CTA: 128x128 tile, 256 threads = 8 warps (4m x 2n), warp tile 32x64.
// K chunks of 32, triple-buffered cp.async, 2 CTAs/SM for cross-CTA overlap.
// ---------------------------------------------------------------------------
#define PITCH 80
#define TILE_B (128 * PITCH)            // 10240 B per operand tile
#define STAGE_B (3 * TILE_B)            // A, Bhi, Blo = 30720 B per stage
#define NSTAGE 3

__global__ __launch_bounds__(256, 2)
void mma_gemm(const __half* __restrict__ A,
              const __half* __restrict__ Bhi0, const __half* __restrict__ Blo0,
              float* __restrict__ C0,
              const __half* __restrict__ Bhi1, const __half* __restrict__ Blo1,
              float* __restrict__ C1)
{
    extern __shared__ char smem[];
    const uint32_t sb = smem_u32(smem);

    const __half* Bhi = blockIdx.z ? Bhi1 : Bhi0;
    const __half* Blo = blockIdx.z ? Blo1 : Blo0;
    float* C = blockIdx.z ? C1 : C0;

    const int tid  = threadIdx.x;
    const int wid  = tid >> 5;
    const int lane = tid & 31;
    const int bm0  = blockIdx.y * 128;
    const int bn0  = blockIdx.x * 128;
    const int wm   = (wid >> 1) * 32;    // warp m offset in tile
    const int wn   = (wid & 1) * 64;     // warp n offset in tile

    float acc[2][8][4];
#pragma unroll
    for (int i = 0; i < 2; i++)
#pragma unroll
        for (int j = 0; j < 8; j++)
#pragma unroll
            for (int r = 0; r < 4; r++) acc[i][j][r] = 0.f;

    // ---- async stage loader: 6 x 16B per thread per stage
    auto load_stage = [&](int s, int k0) {
        const uint32_t base = sb + s * STAGE_B;
#pragma unroll
        for (int i = 0; i < 2; i++) {
            const int idx = tid + 256 * i;        // 0..511
            const int row = idx >> 2;             // 0..127
            const int c   = idx & 3;              // 16B chunk in 64B row
            const uint32_t off = row * PITCH + c * 16;
            const size_t ga = ((size_t)(bm0 + row) * 512 + k0) * 2 + c * 16;
            const size_t gb = ((size_t)(bn0 + row) * 512 + k0) * 2 + c * 16;
            CP16(base + off,              (const char*)A   + ga);
            CP16(base + TILE_B + off,     (const char*)Bhi + gb);
            CP16(base + 2 * TILE_B + off, (const char*)Blo + gb);
        }
        CP_COMMIT();
    };

    // ---- compute one k32 chunk from stage s
    auto compute_stage = [&](int s) {
        const uint32_t base = sb + s * STAGE_B;
#pragma unroll
        for (int kk = 0; kk < 2; kk++) {          // two k16 halves
            const uint32_t koff = kk * 32;        // byte offset of k16 half

            uint32_t a[2][4];
#pragma unroll
            for (int f = 0; f < 2; f++) {
                const uint32_t ra = base +
                    (uint32_t)(wm + f * 16 + (lane & 15)) * PITCH +
                    koff + ((lane >> 4) << 4);
                LDSM4(a[f][0], a[f][1], a[f][2], a[f][3], ra);
            }

            uint32_t bh[8][2], bl[8][2];
#pragma unroll
            for (int g = 0; g < 4; g++) {
                const uint32_t rb = base + TILE_B +
                    (uint32_t)(wn + g * 16 + (lane & 7) + ((lane >> 4) << 3)) * PITCH +
                    koff + (((lane >> 3) & 1) << 4);
                LDSM4(bh[2*g][0], bh[2*g][1], bh[2*g+1][0], bh[2*g+1][1], rb);
                LDSM4(bl[2*g][0], bl[2*g][1], bl[2*g+1][0], bl[2*g+1][1], rb + TILE_B);
            }

#pragma unroll
            for (int f = 0; f < 2; f++)
#pragma unroll
                for (int g = 0; g < 8; g++) {
                    MMA16816F(acc[f][g], a[f], bh[g]);
                    MMA16816F(acc[f][g], a[f], bl[g]);
                }
        }
    };

    load_stage(0, 0);
    load_stage(1, 32);
    load_stage(2, 64);

#pragma unroll
    for (int c = 0; c < 16; c++) {
        if (c <= 13)      { CP_WAIT(2); }
        else if (c == 14) { CP_WAIT(1); }
        else              { CP_WAIT(0); }
        __syncthreads();
        compute_stage(c % NSTAGE);
        if (c + NSTAGE < 16) {
            __syncthreads();
            load_stage(c % NSTAGE, (c + NSTAGE) * 32);
        }
    }

    // ---- epilogue: acc -> C (fp32, row stride 512)
    const int qrow = lane >> 2;          // 0..7
    const int qcol = (lane & 3) * 2;     // 0,2,4,6
#pragma unroll
    for (int f = 0; f < 2; f++)
#pragma unroll
        for (int g = 0; g < 8; g++) {
            const int row = bm0 + wm + f * 16 + qrow;
            const int col = bn0 + wn + g * 8 + qcol;
            *(float2*)(C + (size_t)row * 512 + col) =
                make_float2(acc[f][g][0], acc[f][g][1]);
            *(float2*)(C + (size_t)(row + 8) * 512 + col) =
                make_float2(acc[f][g][2], acc[f][g][3]);
        }
}

// ---------------------------------------------------------------------------
// convT: in fp32 [512][M] (channel-major) -> fp16 [M][512] (transpose+round).
// ---------------------------------------------------------------------------
__global__ __launch_bounds__(256)
void convT_kernel(const float* __restrict__ in, __half* __restrict__ outp, int M)
{
    __shared__ float t[32][33];
    const int tx = threadIdx.x, ty = threadIdx.y;
    const int mb = blockIdx.x * 32, kb = blockIdx.y * 32;
#pragma unroll
    for (int j = 0; j < 4; j++)
        t[ty + 8 * j][tx] = in[(size_t)(kb + ty + 8 * j) * M + mb + tx];
    __syncthreads();
#pragma unroll
    for (int j = 0; j < 4; j++) {
        const float v = t[tx][ty + 8 * j];
        outp[(size_t)(mb + ty + 8 * j) * 512 + kb + tx] = __float2half(v);
    }
}

// ---------------------------------------------------------------------------
// conv_w: all 4 weights in one launch (blockIdx.z selects). fp32 -> hi/lo fp16.
// ---------------------------------------------------------------------------
__global__ __launch_bounds__(256)
void conv_w_kernel(const float4* __restrict__ w0, const float4* __restrict__ w1,
                   const float4* __restrict__ w2, const float4* __restrict__ w3,
                   __half* __restrict__ whi, __half* __restrict__ wlo)
{
    const int z = blockIdx.z;
    const float4* src = (z == 0) ? w0 : (z == 1) ? w1 : (z == 2) ? w2 : w3;
    const int i = blockIdx.x * 256 + threadIdx.x;        // 0..65535
    const float4 v = src[i];

    const __half hx = __float2half(v.x), hy = __float2half(v.y);
    const __half hz = __float2half(v.z), hw = __float2half(v.w);
    const __half lx = __float2half(v.x - __half2float(hx));
    const __half ly = __float2half(v.y - __half2float(hy));
    const __half lz = __float2half(v.z - __half2float(hz));
    const __half lw = __float2half(v.w - __half2float(hw));

    const size_t o = (size_t)z * (DMODEL * DMODEL / 4) + i;
    ((ushort4*)whi)[o] = make_ushort4(__half_as_ushort(hx), __half_as_ushort(hy),
                                      __half_as_ushort(hz), __half_as_ushort(hw));
    ((ushort4*)wlo)[o] = make_ushort4(__half_as_ushort(lx), __half_as_ushort(ly),
                                      __half_as_ushort(lz), __half_as_ushort(lw));
}

// ---------------------------------------------------------------------------
// Windowed attention, 256 threads: tid = head*32 + half*16 + pos.
// (pos,head) pair splits the 64-elem head dim across two same-warp threads
// (shfl_xor 16 combines score partials); each thread emits 32 out channels.
// One block per 4x4 guide tile (shared 3x3 window). Writes fp16.
// ---------------------------------------------------------------------------
__global__ __launch_bounds__(256)
void attn_kernel(const float* __restrict__ Q, const float* __restrict__ Km,
                 const float* __restrict__ Vm, __half* __restrict__ msg)
{
    __shared__ float Ks[9][512];
    __shared__ float Vs[9][512];

    const int tx = blockIdx.x;
    const int ty = blockIdx.y;
    const int tid = threadIdx.x;

    for (int idx = tid; idx < 9 * 128; idx += 256) {
        const int k  = idx >> 7;
        const int c4 = idx & 127;
        const int yy = min(max(ty - 1 + k / 3, 0), 31);
        const int xx = min(max(tx - 1 + k % 3, 0), 31);
        const int p  = yy * 32 + xx;
        ((float4*)&Ks[k][0])[c4] = ((const float4*)(Km + (size_t)p * 512))[c4];
        ((float4*)&Vs[k][0])[c4] = ((const float4*)(Vm + (size_t)p * 512))[c4];
    }
    __syncthreads();

    const int pos  = tid & 15;           // 0..15
    const int half = (tid >> 4) & 1;     // 0..1
    const int head = tid >> 5;           // 0..7
    const int n = (ty * 4 + (pos >> 2)) * 128 + tx * 4 + (pos & 3);
    const int coff = head * 64 + half * 32;   // this thread's 32 channels

    const float4* q4 = (const float4*)(Q + (size_t)n * 512 + coff);

    float acc[9];
#pragma unroll
    for (int k = 0; k < 9; k++) acc[k] = 0.f;

#pragma unroll
    for (int e = 0; e < 8; e++) {
        float4 qv = q4[e];
#pragma unroll
        for (int k = 0; k < 9; k++) {
            float4 kv = ((const float4*)&Ks[k][coff])[e];
            acc[k] += qv.x * kv.x + qv.y * kv.y + qv.z * kv.z + qv.w * kv.w;
        }
    }
    // combine the two halves (threads tid and tid^16 share a warp)
#pragma unroll
    for (int k = 0; k < 9; k++)
        acc[k] += __shfl_xor_sync(0xffffffffu, acc[k], 16);

    float mx = acc[0];
#pragma unroll
    for (int k = 1; k < 9; k++) mx = fmaxf(mx, acc[k]);
    float s = 0.f;
#pragma unroll
    for (int k = 0; k < 9; k++) { acc[k] = __expf(0.125f * (acc[k] - mx)); s += acc[k]; }
    const float inv = 1.f / s;
#pragma unroll
    for (int k = 0; k < 9; k++) acc[k] *= inv;

    __half* outp = msg + (size_t)n * 512 + coff;
#pragma unroll
    for (int e = 0; e < 8; e++) {
        float4 o = make_float4(0.f, 0.f, 0.f, 0.f);
#pragma unroll
        for (int k = 0; k < 9; k++) {
            float4 vv = ((const float4*)&Vs[k][coff])[e];
            o.x += acc[k] * vv.x;
            o.y += acc[k] * vv.y;
            o.z += acc[k] * vv.z;
            o.w += acc[k] * vv.w;
        }
        const __half2 h0 = __floats2half2_rn(o.x, o.y);
        const __half2 h1 = __floats2half2_rn(o.z, o.w);
        uint2 pk;
        pk.x = *(const uint32_t*)&h0;
        pk.y = *(const uint32_t*)&h1;
        *(uint2*)(outp + e * 4) = pk;
    }
}

// ---------------------------------------------------------------------------
// LayerNorm over d=512 per position + transpose to channel-major output.
// ---------------------------------------------------------------------------
__global__ __launch_bounds__(256)
void ln_kernel(const float* __restrict__ X, const float* __restrict__ gamma,
               const float* __restrict__ beta, float* __restrict__ out)
{
    __shared__ float sm[16 * 513];

    const int nb   = blockIdx.x * 16;
    const int warp = threadIdx.x >> 5;
    const int lane = threadIdx.x & 31;

    for (int r = warp; r < 16; r += 8) {
        const int n = nb + r;
        const float* row = X + (size_t)n * 512;
        float v[16];
        float s = 0.f;
#pragma unroll
        for (int j = 0; j < 16; j++) { v[j] = row[lane + 32 * j]; s += v[j]; }
#pragma unroll
        for (int o = 16; o > 0; o >>= 1) s += __shfl_xor_sync(0xffffffffu, s, o);
        const float mu = s * (1.f / 512.f);
        float q = 0.f;
#pragma unroll
        for (int j = 0; j < 16; j++) { float d = v[j] - mu; q += d * d; }
#pragma unroll
        for (int o = 16; o > 0; o >>= 1) q += __shfl_xor_sync(0xffffffffu, q, o);
        const float rstd = rsqrtf(q * (1.f / 512.f) + 1e-5f);
#pragma unroll
        for (int j = 0; j < 16; j++) {
            const int o = lane + 32 * j;
            sm[r * 513 + o] = (v[j] - mu) * rstd * gamma[o] + beta[o];
        }
    }
    __syncthreads();

    const int i  = threadIdx.x & 15;
    const int ob = threadIdx.x >> 4;
    for (int o = ob; o < 512; o += 16)
        out[(size_t)o * 16384 + nb + i] = sm[i * 513 + o];
}

// ---------------------------------------------------------------------------
extern "C" void kernel_launch(void* const* d_in, const int* in_sizes, int n_in,
                              void* d_out, int out_size)
{
    const float* low   = (const float*)d_in[0];
    const float* guide = (const float*)d_in[1];
    const float* Wq    = (const float*)d_in[2];
    const float* Wk    = (const float*)d_in[3];
    const float* Wv    = (const float*)d_in[4];
    const float* Wm    = (const float*)d_in[5];
    const float* gamma = (const float*)d_in[6];
    const float* beta  = (const float*)d_in[7];
    float* out = (float*)d_out;

    __half *Af, *Lf, *Whi, *Wlo;
    float *Q, *K, *V, *M2;
    cudaGetSymbolAddress((void**)&Af,  g_Af);
    cudaGetSymbolAddress((void**)&Lf,  g_Lf);
    cudaGetSymbolAddress((void**)&Whi, g_Whi);
    cudaGetSymbolAddress((void**)&Wlo, g_Wlo);
    cudaGetSymbolAddress((void**)&Q,   g_Q);
    cudaGetSymbolAddress((void**)&K,   g_K);
    cudaGetSymbolAddress((void**)&V,   g_V);
    cudaGetSymbolAddress((void**)&M2,  g_M2);

    const int W_ELEMS = DMODEL * DMODEL;       // 262144
    const int GEMM_SMEM = NSTAGE * STAGE_B;    // 92160 B

    cudaFuncSetAttribute(mma_gemm, cudaFuncAttributeMaxDynamicSharedMemorySize,
                         GEMM_SMEM);

    // Convert + transpose activations (channel-major fp32 -> row-major fp16)
    convT_kernel<<<dim3(NPOS / 32, 16), dim3(32, 8)>>>(guide, Af, NPOS);
    convT_kernel<<<dim3(LPOS / 32, 16), dim3(32, 8)>>>(low, Lf, LPOS);

    // Convert all 4 weights in one launch: slots 0=Wq, 1=Wk, 2=Wv, 3=Wm
    conv_w_kernel<<<dim3(W_ELEMS / 4 / 256, 1, 4), 256>>>(
        (const float4*)Wq, (const float4*)Wk, (const float4*)Wv, (const float4*)Wm,
        Whi, Wlo);

    // Q = guide @ Wq^T : grid (N/128=4, M/128=128)
    mma_gemm<<<dim3(4, 128, 1), 256, GEMM_SMEM>>>(
        Af, Whi, Wlo, Q, Whi, Wlo, Q);
    // K,V = low @ {Wk,Wv}^T fused via z: grid (4, 8, 2)
    mma_gemm<<<dim3(4, 8, 2), 256, GEMM_SMEM>>>(
        Lf,
        Whi + 1 * W_ELEMS, Wlo + 1 * W_ELEMS, K,
        Whi + 2 * W_ELEMS, Wlo + 2 * W_ELEMS, V);

    // Windowed attention -> fp16 msg directly into Af (guide no longer needed)
    attn_kernel<<<dim3(32, 32), 256>>>(Q, K, V, Af);

    // M2 = msg @ Wm^T
    mma_gemm<<<dim3(4, 128, 1), 256, GEMM_SMEM>>>(
        Af, Whi + 3 * W_ELEMS, Wlo + 3 * W_ELEMS, M2,
        Whi + 3 * W_ELEMS, Wlo + 3 * W_ELEMS, M2);

    // LayerNorm + transpose to channel-major output
    ln_kernel<<<1024, 256>>>(M2, gamma, beta, out);
}

// round 7
// speedup vs baseline: 4.3033x; 1.1001x over previous
#include <cuda_runtime.h>
#include <cuda_fp16.h>
#include <cstdint>

#define NPOS 16384   // 128*128 guide positions
#define LPOS 1024    // 32*32 low positions
#define DMODEL 512

// ---------------------------------------------------------------------------
// Scratch (static device globals — no allocation APIs allowed)
// ---------------------------------------------------------------------------
__device__ __half g_Af [NPOS * DMODEL];          // fp16 activations (guide, then msg)
__device__ __half g_Lf [LPOS * DMODEL];          // fp16 low activations
__device__ __half g_Whi[4 * DMODEL * DMODEL];    // weight hi (fp16)
__device__ __half g_Wlo[4 * DMODEL * DMODEL];    // weight lo (fp16 residual)
__device__ float g_Q [NPOS * DMODEL];
__device__ float g_K [LPOS * DMODEL];
__device__ float g_V [LPOS * DMODEL];
__device__ float g_M2[NPOS * DMODEL];

// ---------------------------------------------------------------------------
// Baseline-PTX helpers (sm_80+ features only: work on plain sm_103 target)
// ---------------------------------------------------------------------------
__device__ __forceinline__ uint32_t smem_u32(const void* p) {
    uint32_t a;
    asm("{ .reg .u64 t; cvta.to.shared.u64 t, %1; cvt.u32.u64 %0, t; }" : "=r"(a) : "l"(p));
    return a;
}

#define CP16(dst, src) \
    asm volatile("cp.async.cg.shared.global [%0], [%1], 16;" :: "r"(dst), "l"(src))
#define CP_COMMIT() asm volatile("cp.async.commit_group;" ::: "memory")
#define CP_WAIT(n)  asm volatile("cp.async.wait_group %0;" :: "n"(n) : "memory")

#define LDSM4(r0, r1, r2, r3, addr) \
    asm volatile("ldmatrix.sync.aligned.m8n8.x4.shared.b16 {%0,%1,%2,%3}, [%4];" \
        : "=r"(r0), "=r"(r1), "=r"(r2), "=r"(r3) : "r"(addr))

#define MMA16816F(d, a, b) \
    asm volatile("mma.sync.aligned.m16n8k16.row.col.f32.f16.f16.f32 " \
        "{%0,%1,%2,%3}, {%4,%5,%6,%7}, {%8,%9}, {%0,%1,%2,%3};" \
        : "+f"((d)[0]), "+f"((d)[1]), "+f"((d)[2]), "+f"((d)[3]) \
        : "r"((a)[0]), "r"((a)[1]), "r"((a)[2]), "r"((a)[3]), \
          "r"((b)[0]), "r"((b)[1]))

// ---------------------------------------------------------------------------
// mma_gemm: C[m][n] = sum_k A[m][k]*B[n][k], K=512 fixed.
// fp32 emulation: A rounded to fp16, B = Bhi + Blo fp16 split (exact):
//   C = A*Bhi + A*Blo, fp32 accumulate.
// CTA: 128x128 tile, 128 threads = 4 warps (2m x 2n), warp tile 64x64
// (12 LDSM feed 64 MMAs per k16 -> long MMA bursts keep tensor pipe full).
// K chunks of 32, triple-buffered cp.async, 2 CTAs/SM.
// Three independent GEMMs selected by blockIdx.z (args structs); CTAs with
// blockIdx.y >= mtiles exit immediately (lets QKV share one launch).
// ---------------------------------------------------------------------------
#define PITCH 80
#define TILE_B (128 * PITCH)            // 10240 B per operand tile
#define STAGE_B (3 * TILE_B)            // A, Bhi, Blo = 30720 B per stage
#define NSTAGE 3

struct GemmArgs {
    const __half* A;
    const __half* Bhi;
    const __half* Blo;
    float* C;
    int mtiles;
};

__global__ __launch_bounds__(128, 2)
void mma_gemm(GemmArgs g0, GemmArgs g1, GemmArgs g2)
{
    const GemmArgs& ga_ = (blockIdx.z == 0) ? g0 : (blockIdx.z == 1) ? g1 : g2;
    if ((int)blockIdx.y >= ga_.mtiles) return;

    const __half* __restrict__ A   = ga_.A;
    const __half* __restrict__ Bhi = ga_.Bhi;
    const __half* __restrict__ Blo = ga_.Blo;
    float* __restrict__ C = ga_.C;

    extern __shared__ char smem[];
    const uint32_t sb = smem_u32(smem);

    const int tid  = threadIdx.x;
    const int wid  = tid >> 5;
    const int lane = tid & 31;
    const int bm0  = blockIdx.y * 128;
    const int bn0  = blockIdx.x * 128;
    const int wm   = (wid >> 1) * 64;    // warp m offset in tile
    const int wn   = (wid & 1) * 64;     // warp n offset in tile

    float acc[4][8][4];
#pragma unroll
    for (int i = 0; i < 4; i++)
#pragma unroll
        for (int j = 0; j < 8; j++)
#pragma unroll
            for (int r = 0; r < 4; r++) acc[i][j][r] = 0.f;

    // ---- async stage loader: 12 x 16B per thread per stage
    auto load_stage = [&](int s, int k0) {
        const uint32_t base = sb + s * STAGE_B;
#pragma unroll
        for (int i = 0; i < 4; i++) {
            const int idx = tid + 128 * i;        // 0..511
            const int row = idx >> 2;             // 0..127
            const int c   = idx & 3;              // 16B chunk in 64B row
            const uint32_t off = row * PITCH + c * 16;
            const size_t ga = ((size_t)(bm0 + row) * 512 + k0) * 2 + c * 16;
            const size_t gb = ((size_t)(bn0 + row) * 512 + k0) * 2 + c * 16;
            CP16(base + off,              (const char*)A   + ga);
            CP16(base + TILE_B + off,     (const char*)Bhi + gb);
            CP16(base + 2 * TILE_B + off, (const char*)Blo + gb);
        }
        CP_COMMIT();
    };

    // ---- compute one k32 chunk from stage s
    auto compute_stage = [&](int s) {
        const uint32_t base = sb + s * STAGE_B;
#pragma unroll
        for (int kk = 0; kk < 2; kk++) {          // two k16 halves
            const uint32_t koff = kk * 32;        // byte offset of k16 half

            uint32_t a[4][4];
#pragma unroll
            for (int f = 0; f < 4; f++) {
                const uint32_t ra = base +
                    (uint32_t)(wm + f * 16 + (lane & 15)) * PITCH +
                    koff + ((lane >> 4) << 4);
                LDSM4(a[f][0], a[f][1], a[f][2], a[f][3], ra);
            }

            uint32_t bh[8][2], bl[8][2];
#pragma unroll
            for (int g = 0; g < 4; g++) {
                const uint32_t rb = base + TILE_B +
                    (uint32_t)(wn + g * 16 + (lane & 7) + ((lane >> 4) << 3)) * PITCH +
                    koff + (((lane >> 3) & 1) << 4);
                LDSM4(bh[2*g][0], bh[2*g][1], bh[2*g+1][0], bh[2*g+1][1], rb);
                LDSM4(bl[2*g][0], bl[2*g][1], bl[2*g+1][0], bl[2*g+1][1], rb + TILE_B);
            }

#pragma unroll
            for (int f = 0; f < 4; f++)
#pragma unroll
                for (int g = 0; g < 8; g++) {
                    MMA16816F(acc[f][g], a[f], bh[g]);
                    MMA16816F(acc[f][g], a[f], bl[g]);
                }
        }
    };

    load_stage(0, 0);
    load_stage(1, 32);
    load_stage(2, 64);

#pragma unroll
    for (int c = 0; c < 16; c++) {
        if (c <= 13)      { CP_WAIT(2); }
        else if (c == 14) { CP_WAIT(1); }
        else              { CP_WAIT(0); }
        __syncthreads();
        compute_stage(c % NSTAGE);
        if (c + NSTAGE < 16) {
            __syncthreads();
            load_stage(c % NSTAGE, (c + NSTAGE) * 32);
        }
    }

    // ---- epilogue: acc -> C (fp32, row stride 512)
    const int qrow = lane >> 2;          // 0..7
    const int qcol = (lane & 3) * 2;     // 0,2,4,6
#pragma unroll
    for (int f = 0; f < 4; f++)
#pragma unroll
        for (int g = 0; g < 8; g++) {
            const int row = bm0 + wm + f * 16 + qrow;
            const int col = bn0 + wn + g * 8 + qcol;
            *(float2*)(C + (size_t)row * 512 + col) =
                make_float2(acc[f][g][0], acc[f][g][1]);
            *(float2*)(C + (size_t)(row + 8) * 512 + col) =
                make_float2(acc[f][g][2], acc[f][g][3]);
        }
}

// ---------------------------------------------------------------------------
// convT: in fp32 [512][M] (channel-major) -> fp16 [M][512] (transpose+round).
// ---------------------------------------------------------------------------
__global__ __launch_bounds__(256)
void convT_kernel(const float* __restrict__ in, __half* __restrict__ outp, int M)
{
    __shared__ float t[32][33];
    const int tx = threadIdx.x, ty = threadIdx.y;
    const int mb = blockIdx.x * 32, kb = blockIdx.y * 32;
#pragma unroll
    for (int j = 0; j < 4; j++)
        t[ty + 8 * j][tx] = in[(size_t)(kb + ty + 8 * j) * M + mb + tx];
    __syncthreads();
#pragma unroll
    for (int j = 0; j < 4; j++) {
        const float v = t[tx][ty + 8 * j];
        outp[(size_t)(mb + ty + 8 * j) * 512 + kb + tx] = __float2half(v);
    }
}

// ---------------------------------------------------------------------------
// conv_w: all 4 weights in one launch (blockIdx.z selects). fp32 -> hi/lo fp16.
// ---------------------------------------------------------------------------
__global__ __launch_bounds__(256)
void conv_w_kernel(const float4* __restrict__ w0, const float4* __restrict__ w1,
                   const float4* __restrict__ w2, const float4* __restrict__ w3,
                   __half* __restrict__ whi, __half* __restrict__ wlo)
{
    const int z = blockIdx.z;
    const float4* src = (z == 0) ? w0 : (z == 1) ? w1 : (z == 2) ? w2 : w3;
    const int i = blockIdx.x * 256 + threadIdx.x;        // 0..65535
    const float4 v = src[i];

    const __half hx = __float2half(v.x), hy = __float2half(v.y);
    const __half hz = __float2half(v.z), hw = __float2half(v.w);
    const __half lx = __float2half(v.x - __half2float(hx));
    const __half ly = __float2half(v.y - __half2float(hy));
    const __half lz = __float2half(v.z - __half2float(hz));
    const __half lw = __float2half(v.w - __half2float(hw));

    const size_t o = (size_t)z * (DMODEL * DMODEL / 4) + i;
    ((ushort4*)whi)[o] = make_ushort4(__half_as_ushort(hx), __half_as_ushort(hy),
                                      __half_as_ushort(hz), __half_as_ushort(hw));
    ((ushort4*)wlo)[o] = make_ushort4(__half_as_ushort(lx), __half_as_ushort(ly),
                                      __half_as_ushort(lz), __half_as_ushort(lw));
}

// ---------------------------------------------------------------------------
// Windowed attention, 256 threads: tid = head*32 + half*16 + pos.
// (pos,head) pair splits the 64-elem head dim across two same-warp threads
// (shfl_xor 16 combines score partials); each thread emits 32 out channels.
// One block per 4x4 guide tile (shared 3x3 window). Writes fp16.
// ---------------------------------------------------------------------------
__global__ __launch_bounds__(256)
void attn_kernel(const float* __restrict__ Q, const float* __restrict__ Km,
                 const float* __restrict__ Vm, __half* __restrict__ msg)
{
    __shared__ float Ks[9][512];
    __shared__ float Vs[9][512];

    const int tx = blockIdx.x;
    const int ty = blockIdx.y;
    const int tid = threadIdx.x;

    for (int idx = tid; idx < 9 * 128; idx += 256) {
        const int k  = idx >> 7;
        const int c4 = idx & 127;
        const int yy = min(max(ty - 1 + k / 3, 0), 31);
        const int xx = min(max(tx - 1 + k % 3, 0), 31);
        const int p  = yy * 32 + xx;
        ((float4*)&Ks[k][0])[c4] = ((const float4*)(Km + (size_t)p * 512))[c4];
        ((float4*)&Vs[k][0])[c4] = ((const float4*)(Vm + (size_t)p * 512))[c4];
    }
    __syncthreads();

    const int pos  = tid & 15;           // 0..15
    const int half = (tid >> 4) & 1;     // 0..1
    const int head = tid >> 5;           // 0..7
    const int n = (ty * 4 + (pos >> 2)) * 128 + tx * 4 + (pos & 3);
    const int coff = head * 64 + half * 32;   // this thread's 32 channels

    const float4* q4 = (const float4*)(Q + (size_t)n * 512 + coff);

    float acc[9];
#pragma unroll
    for (int k = 0; k < 9; k++) acc[k] = 0.f;

#pragma unroll
    for (int e = 0; e < 8; e++) {
        float4 qv = q4[e];
#pragma unroll
        for (int k = 0; k < 9; k++) {
            float4 kv = ((const float4*)&Ks[k][coff])[e];
            acc[k] += qv.x * kv.x + qv.y * kv.y + qv.z * kv.z + qv.w * kv.w;
        }
    }
    // combine the two halves (threads tid and tid^16 share a warp)
#pragma unroll
    for (int k = 0; k < 9; k++)
        acc[k] += __shfl_xor_sync(0xffffffffu, acc[k], 16);

    float mx = acc[0];
#pragma unroll
    for (int k = 1; k < 9; k++) mx = fmaxf(mx, acc[k]);
    float s = 0.f;
#pragma unroll
    for (int k = 0; k < 9; k++) { acc[k] = __expf(0.125f * (acc[k] - mx)); s += acc[k]; }
    const float inv = 1.f / s;
#pragma unroll
    for (int k = 0; k < 9; k++) acc[k] *= inv;

    __half* outp = msg + (size_t)n * 512 + coff;
#pragma unroll
    for (int e = 0; e < 8; e++) {
        float4 o = make_float4(0.f, 0.f, 0.f, 0.f);
#pragma unroll
        for (int k = 0; k < 9; k++) {
            float4 vv = ((const float4*)&Vs[k][coff])[e];
            o.x += acc[k] * vv.x;
            o.y += acc[k] * vv.y;
            o.z += acc[k] * vv.z;
            o.w += acc[k] * vv.w;
        }
        const __half2 h0 = __floats2half2_rn(o.x, o.y);
        const __half2 h1 = __floats2half2_rn(o.z, o.w);
        uint2 pk;
        pk.x = *(const uint32_t*)&h0;
        pk.y = *(const uint32_t*)&h1;
        *(uint2*)(outp + e * 4) = pk;
    }
}

// ---------------------------------------------------------------------------
// LayerNorm over d=512 per position + transpose to channel-major output.
// ---------------------------------------------------------------------------
__global__ __launch_bounds__(256)
void ln_kernel(const float* __restrict__ X, const float* __restrict__ gamma,
               const float* __restrict__ beta, float* __restrict__ out)
{
    __shared__ float sm[16 * 513];

    const int nb   = blockIdx.x * 16;
    const int warp = threadIdx.x >> 5;
    const int lane = threadIdx.x & 31;

    for (int r = warp; r < 16; r += 8) {
        const int n = nb + r;
        const float* row = X + (size_t)n * 512;
        float v[16];
        float s = 0.f;
#pragma unroll
        for (int j = 0; j < 16; j++) { v[j] = row[lane + 32 * j]; s += v[j]; }
#pragma unroll
        for (int o = 16; o > 0; o >>= 1) s += __shfl_xor_sync(0xffffffffu, s, o);
        const float mu = s * (1.f / 512.f);
        float q = 0.f;
#pragma unroll
        for (int j = 0; j < 16; j++) { float d = v[j] - mu; q += d * d; }
#pragma unroll
        for (int o = 16; o > 0; o >>= 1) q += __shfl_xor_sync(0xffffffffu, q, o);
        const float rstd = rsqrtf(q * (1.f / 512.f) + 1e-5f);
#pragma unroll
        for (int j = 0; j < 16; j++) {
            const int o = lane + 32 * j;
            sm[r * 513 + o] = (v[j] - mu) * rstd * gamma[o] + beta[o];
        }
    }
    __syncthreads();

    const int i  = threadIdx.x & 15;
    const int ob = threadIdx.x >> 4;
    for (int o = ob; o < 512; o += 16)
        out[(size_t)o * 16384 + nb + i] = sm[i * 513 + o];
}

// ---------------------------------------------------------------------------
extern "C" void kernel_launch(void* const* d_in, const int* in_sizes, int n_in,
                              void* d_out, int out_size)
{
    const float* low   = (const float*)d_in[0];
    const float* guide = (const float*)d_in[1];
    const float* Wq    = (const float*)d_in[2];
    const float* Wk    = (const float*)d_in[3];
    const float* Wv    = (const float*)d_in[4];
    const float* Wm    = (const float*)d_in[5];
    const float* gamma = (const float*)d_in[6];
    const float* beta  = (const float*)d_in[7];
    float* out = (float*)d_out;

    __half *Af, *Lf, *Whi, *Wlo;
    float *Q, *K, *V, *M2;
    cudaGetSymbolAddress((void**)&Af,  g_Af);
    cudaGetSymbolAddress((void**)&Lf,  g_Lf);
    cudaGetSymbolAddress((void**)&Whi, g_Whi);
    cudaGetSymbolAddress((void**)&Wlo, g_Wlo);
    cudaGetSymbolAddress((void**)&Q,   g_Q);
    cudaGetSymbolAddress((void**)&K,   g_K);
    cudaGetSymbolAddress((void**)&V,   g_V);
    cudaGetSymbolAddress((void**)&M2,  g_M2);

    const int W_ELEMS = DMODEL * DMODEL;       // 262144
    const int GEMM_SMEM = NSTAGE * STAGE_B;    // 92160 B

    cudaFuncSetAttribute(mma_gemm, cudaFuncAttributeMaxDynamicSharedMemorySize,
                         GEMM_SMEM);

    // Convert + transpose activations (channel-major fp32 -> row-major fp16)
    convT_kernel<<<dim3(NPOS / 32, 16), dim3(32, 8)>>>(guide, Af, NPOS);
    convT_kernel<<<dim3(LPOS / 32, 16), dim3(32, 8)>>>(low, Lf, LPOS);

    // Convert all 4 weights in one launch: slots 0=Wq, 1=Wk, 2=Wv, 3=Wm
    conv_w_kernel<<<dim3(W_ELEMS / 4 / 256, 1, 4), 256>>>(
        (const float4*)Wq, (const float4*)Wk, (const float4*)Wv, (const float4*)Wm,
        Whi, Wlo);

    // Q, K, V projections in ONE launch (z selects; y-overrun CTAs exit)
    {
        GemmArgs gq = { Af, Whi,               Wlo,               Q, 128 };
        GemmArgs gk = { Lf, Whi + 1 * W_ELEMS, Wlo + 1 * W_ELEMS, K, 8 };
        GemmArgs gv = { Lf, Whi + 2 * W_ELEMS, Wlo + 2 * W_ELEMS, V, 8 };
        mma_gemm<<<dim3(4, 128, 3), 128, GEMM_SMEM>>>(gq, gk, gv);
    }

    // Windowed attention -> fp16 msg directly into Af (guide no longer needed)
    attn_kernel<<<dim3(32, 32), 256>>>(Q, K, V, Af);

    // M2 = msg @ Wm^T
    {
        GemmArgs gm = { Af, Whi + 3 * W_ELEMS, Wlo + 3 * W_ELEMS, M2, 128 };
        mma_gemm<<<dim3(4, 128, 1), 128, GEMM_SMEM>>>(gm, gm, gm);
    }

    // LayerNorm + transpose to channel-major output
    ln_kernel<<<1024, 256>>>(M2, gamma, beta, out);
}

// round 8
// speedup vs baseline: 4.3670x; 1.0148x over previous
#include <cuda_runtime.h>
#include <cuda_fp16.h>
#include <cstdint>

#define NPOS 16384   // 128*128 guide positions
#define LPOS 1024    // 32*32 low positions
#define DMODEL 512

// ---------------------------------------------------------------------------
// Scratch (static device globals — no allocation APIs allowed)
// ---------------------------------------------------------------------------
__device__ __half g_Af [NPOS * DMODEL];          // fp16 activations (guide, then msg)
__device__ __half g_Lf [LPOS * DMODEL];          // fp16 low activations
__device__ __half g_Whi[4 * DMODEL * DMODEL];    // weight hi (fp16)
__device__ __half g_Wlo[4 * DMODEL * DMODEL];    // weight lo (fp16 residual)
__device__ float g_Q [NPOS * DMODEL];
__device__ float g_K [LPOS * DMODEL];
__device__ float g_V [LPOS * DMODEL];
__device__ float g_M2[NPOS * DMODEL];

// ---------------------------------------------------------------------------
// Baseline-PTX helpers (sm_80+ features only: work on plain sm_103 target)
// ---------------------------------------------------------------------------
__device__ __forceinline__ uint32_t smem_u32(const void* p) {
    uint32_t a;
    asm("{ .reg .u64 t; cvta.to.shared.u64 t, %1; cvt.u32.u64 %0, t; }" : "=r"(a) : "l"(p));
    return a;
}

#define CP16(dst, src) \
    asm volatile("cp.async.cg.shared.global [%0], [%1], 16;" :: "r"(dst), "l"(src))
#define CP_COMMIT() asm volatile("cp.async.commit_group;" ::: "memory")
#define CP_WAIT(n)  asm volatile("cp.async.wait_group %0;" :: "n"(n) : "memory")

#define LDSM4(r0, r1, r2, r3, addr) \
    asm volatile("ldmatrix.sync.aligned.m8n8.x4.shared.b16 {%0,%1,%2,%3}, [%4];" \
        : "=r"(r0), "=r"(r1), "=r"(r2), "=r"(r3) : "r"(addr))

#define MMA16816F(d, a, b) \
    asm volatile("mma.sync.aligned.m16n8k16.row.col.f32.f16.f16.f32 " \
        "{%0,%1,%2,%3}, {%4,%5,%6,%7}, {%8,%9}, {%0,%1,%2,%3};" \
        : "+f"((d)[0]), "+f"((d)[1]), "+f"((d)[2]), "+f"((d)[3]) \
        : "r"((a)[0]), "r"((a)[1]), "r"((a)[2]), "r"((a)[3]), \
          "r"((b)[0]), "r"((b)[1]))

// ---------------------------------------------------------------------------
// mma_gemm: C[m][n] = sum_k A[m][k]*B[n][k], K=512 fixed.
// fp32 emulation: A rounded to fp16, B = Bhi + Blo fp16 split (exact):
//   C = A*Bhi + A*Blo, fp32 accumulate.
// CTA: 128x128 tile, 128 threads = 4 warps (2m x 2n), warp tile 64x64.
// K chunks of 32, 3 smem buffers, SINGLE barrier per chunk: at iter c one
// __syncthreads covers both RAW (chunk c data, after CP_WAIT) and WAR
// (buffer (c+2)%3 was last read at iter c-1); the cp.async for chunk c+2 is
// issued right after the barrier, ~2 chunk-computes before it is consumed.
// Three independent GEMMs selected by blockIdx.z; CTAs with
// blockIdx.y >= mtiles exit immediately (QKV share one launch).
// ---------------------------------------------------------------------------
#define PITCH 80
#define TILE_B (128 * PITCH)            // 10240 B per operand tile
#define STAGE_B (3 * TILE_B)            // A, Bhi, Blo = 30720 B per stage
#define NSTAGE 3

struct GemmArgs {
    const __half* A;
    const __half* Bhi;
    const __half* Blo;
    float* C;
    int mtiles;
};

__global__ __launch_bounds__(128, 2)
void mma_gemm(GemmArgs g0, GemmArgs g1, GemmArgs g2)
{
    const GemmArgs& ga_ = (blockIdx.z == 0) ? g0 : (blockIdx.z == 1) ? g1 : g2;
    if ((int)blockIdx.y >= ga_.mtiles) return;

    const __half* __restrict__ A   = ga_.A;
    const __half* __restrict__ Bhi = ga_.Bhi;
    const __half* __restrict__ Blo = ga_.Blo;
    float* __restrict__ C = ga_.C;

    extern __shared__ char smem[];
    const uint32_t sb = smem_u32(smem);

    const int tid  = threadIdx.x;
    const int wid  = tid >> 5;
    const int lane = tid & 31;
    const int bm0  = blockIdx.y * 128;
    const int bn0  = blockIdx.x * 128;
    const int wm   = (wid >> 1) * 64;    // warp m offset in tile
    const int wn   = (wid & 1) * 64;     // warp n offset in tile

    float acc[4][8][4];
#pragma unroll
    for (int i = 0; i < 4; i++)
#pragma unroll
        for (int j = 0; j < 8; j++)
#pragma unroll
            for (int r = 0; r < 4; r++) acc[i][j][r] = 0.f;

    // ---- async stage loader: 12 x 16B per thread per stage
    auto load_stage = [&](int s, int k0) {
        const uint32_t base = sb + s * STAGE_B;
#pragma unroll
        for (int i = 0; i < 4; i++) {
            const int idx = tid + 128 * i;        // 0..511
            const int row = idx >> 2;             // 0..127
            const int c   = idx & 3;              // 16B chunk in 64B row
            const uint32_t off = row * PITCH + c * 16;
            const size_t ga = ((size_t)(bm0 + row) * 512 + k0) * 2 + c * 16;
            const size_t gb = ((size_t)(bn0 + row) * 512 + k0) * 2 + c * 16;
            CP16(base + off,              (const char*)A   + ga);
            CP16(base + TILE_B + off,     (const char*)Bhi + gb);
            CP16(base + 2 * TILE_B + off, (const char*)Blo + gb);
        }
        CP_COMMIT();
    };

    // ---- compute one k32 chunk from stage s
    auto compute_stage = [&](int s) {
        const uint32_t base = sb + s * STAGE_B;
#pragma unroll
        for (int kk = 0; kk < 2; kk++) {          // two k16 halves
            const uint32_t koff = kk * 32;        // byte offset of k16 half

            uint32_t a[4][4];
#pragma unroll
            for (int f = 0; f < 4; f++) {
                const uint32_t ra = base +
                    (uint32_t)(wm + f * 16 + (lane & 15)) * PITCH +
                    koff + ((lane >> 4) << 4);
                LDSM4(a[f][0], a[f][1], a[f][2], a[f][3], ra);
            }

            uint32_t bh[8][2], bl[8][2];
#pragma unroll
            for (int g = 0; g < 4; g++) {
                const uint32_t rb = base + TILE_B +
                    (uint32_t)(wn + g * 16 + (lane & 7) + ((lane >> 4) << 3)) * PITCH +
                    koff + (((lane >> 3) & 1) << 4);
                LDSM4(bh[2*g][0], bh[2*g][1], bh[2*g+1][0], bh[2*g+1][1], rb);
                LDSM4(bl[2*g][0], bl[2*g][1], bl[2*g+1][0], bl[2*g+1][1], rb + TILE_B);
            }

#pragma unroll
            for (int f = 0; f < 4; f++)
#pragma unroll
                for (int g = 0; g < 8; g++) {
                    MMA16816F(acc[f][g], a[f], bh[g]);
                    MMA16816F(acc[f][g], a[f], bl[g]);
                }
        }
    };

    // ---- prologue: 2 chunks in flight
    load_stage(0, 0);
    load_stage(1, 32);

#pragma unroll
    for (int c = 0; c < 16; c++) {
        if (c < 15) { CP_WAIT(1); } else { CP_WAIT(0); }
        __syncthreads();
        if (c + 2 < 16) load_stage((c + 2) % NSTAGE, (c + 2) * 32);
        compute_stage(c % NSTAGE);
    }

    // ---- epilogue: acc -> C (fp32, row stride 512)
    const int qrow = lane >> 2;          // 0..7
    const int qcol = (lane & 3) * 2;     // 0,2,4,6
#pragma unroll
    for (int f = 0; f < 4; f++)
#pragma unroll
        for (int g = 0; g < 8; g++) {
            const int row = bm0 + wm + f * 16 + qrow;
            const int col = bn0 + wn + g * 8 + qcol;
            *(float2*)(C + (size_t)row * 512 + col) =
                make_float2(acc[f][g][0], acc[f][g][1]);
            *(float2*)(C + (size_t)(row + 8) * 512 + col) =
                make_float2(acc[f][g][2], acc[f][g][3]);
        }
}

// ---------------------------------------------------------------------------
// convT: in fp32 [512][M] (channel-major) -> fp16 [M][512] (transpose+round).
// ---------------------------------------------------------------------------
__global__ __launch_bounds__(256)
void convT_kernel(const float* __restrict__ in, __half* __restrict__ outp, int M)
{
    __shared__ float t[32][33];
    const int tx = threadIdx.x, ty = threadIdx.y;
    const int mb = blockIdx.x * 32, kb = blockIdx.y * 32;
#pragma unroll
    for (int j = 0; j < 4; j++)
        t[ty + 8 * j][tx] = in[(size_t)(kb + ty + 8 * j) * M + mb + tx];
    __syncthreads();
#pragma unroll
    for (int j = 0; j < 4; j++) {
        const float v = t[tx][ty + 8 * j];
        outp[(size_t)(mb + ty + 8 * j) * 512 + kb + tx] = __float2half(v);
    }
}

// ---------------------------------------------------------------------------
// conv_w: all 4 weights in one launch (blockIdx.z selects). fp32 -> hi/lo fp16.
// ---------------------------------------------------------------------------
__global__ __launch_bounds__(256)
void conv_w_kernel(const float4* __restrict__ w0, const float4* __restrict__ w1,
                   const float4* __restrict__ w2, const float4* __restrict__ w3,
                   __half* __restrict__ whi, __half* __restrict__ wlo)
{
    const int z = blockIdx.z;
    const float4* src = (z == 0) ? w0 : (z == 1) ? w1 : (z == 2) ? w2 : w3;
    const int i = blockIdx.x * 256 + threadIdx.x;        // 0..65535
    const float4 v = src[i];

    const __half hx = __float2half(v.x), hy = __float2half(v.y);
    const __half hz = __float2half(v.z), hw = __float2half(v.w);
    const __half lx = __float2half(v.x - __half2float(hx));
    const __half ly = __float2half(v.y - __half2float(hy));
    const __half lz = __float2half(v.z - __half2float(hz));
    const __half lw = __float2half(v.w - __half2float(hw));

    const size_t o = (size_t)z * (DMODEL * DMODEL / 4) + i;
    ((ushort4*)whi)[o] = make_ushort4(__half_as_ushort(hx), __half_as_ushort(hy),
                                      __half_as_ushort(hz), __half_as_ushort(hw));
    ((ushort4*)wlo)[o] = make_ushort4(__half_as_ushort(lx), __half_as_ushort(ly),
                                      __half_as_ushort(lz), __half_as_ushort(lw));
}

// ---------------------------------------------------------------------------
// Windowed attention, 256 threads: tid = head*32 + half*16 + pos.
// (pos,head) pair splits the 64-elem head dim across two same-warp threads
// (shfl_xor 16 combines score partials); each thread emits 32 out channels.
// One block per 4x4 guide tile (shared 3x3 window). Writes fp16.
// ---------------------------------------------------------------------------
__global__ __launch_bounds__(256)
void attn_kernel(const float* __restrict__ Q, const float* __restrict__ Km,
                 const float* __restrict__ Vm, __half* __restrict__ msg)
{
    __shared__ float Ks[9][512];
    __shared__ float Vs[9][512];

    const int tx = blockIdx.x;
    const int ty = blockIdx.y;
    const int tid = threadIdx.x;

    for (int idx = tid; idx < 9 * 128; idx += 256) {
        const int k  = idx >> 7;
        const int c4 = idx & 127;
        const int yy = min(max(ty - 1 + k / 3, 0), 31);
        const int xx = min(max(tx - 1 + k % 3, 0), 31);
        const int p  = yy * 32 + xx;
        ((float4*)&Ks[k][0])[c4] = ((const float4*)(Km + (size_t)p * 512))[c4];
        ((float4*)&Vs[k][0])[c4] = ((const float4*)(Vm + (size_t)p * 512))[c4];
    }
    __syncthreads();

    const int pos  = tid & 15;           // 0..15
    const int half = (tid >> 4) & 1;     // 0..1
    const int head = tid >> 5;           // 0..7
    const int n = (ty * 4 + (pos >> 2)) * 128 + tx * 4 + (pos & 3);
    const int coff = head * 64 + half * 32;   // this thread's 32 channels

    const float4* q4 = (const float4*)(Q + (size_t)n * 512 + coff);

    float acc[9];
#pragma unroll
    for (int k = 0; k < 9; k++) acc[k] = 0.f;

#pragma unroll
    for (int e = 0; e < 8; e++) {
        float4 qv = q4[e];
#pragma unroll
        for (int k = 0; k < 9; k++) {
            float4 kv = ((const float4*)&Ks[k][coff])[e];
            acc[k] += qv.x * kv.x + qv.y * kv.y + qv.z * kv.z + qv.w * kv.w;
        }
    }
    // combine the two halves (threads tid and tid^16 share a warp)
#pragma unroll
    for (int k = 0; k < 9; k++)
        acc[k] += __shfl_xor_sync(0xffffffffu, acc[k], 16);

    float mx = acc[0];
#pragma unroll
    for (int k = 1; k < 9; k++) mx = fmaxf(mx, acc[k]);
    float s = 0.f;
#pragma unroll
    for (int k = 0; k < 9; k++) { acc[k] = __expf(0.125f * (acc[k] - mx)); s += acc[k]; }
    const float inv = 1.f / s;
#pragma unroll
    for (int k = 0; k < 9; k++) acc[k] *= inv;

    __half* outp = msg + (size_t)n * 512 + coff;
#pragma unroll
    for (int e = 0; e < 8; e++) {
        float4 o = make_float4(0.f, 0.f, 0.f, 0.f);
#pragma unroll
        for (int k = 0; k < 9; k++) {
            float4 vv = ((const float4*)&Vs[k][coff])[e];
            o.x += acc[k] * vv.x;
            o.y += acc[k] * vv.y;
            o.z += acc[k] * vv.z;
            o.w += acc[k] * vv.w;
        }
        const __half2 h0 = __floats2half2_rn(o.x, o.y);
        const __half2 h1 = __floats2half2_rn(o.z, o.w);
        uint2 pk;
        pk.x = *(const uint32_t*)&h0;
        pk.y = *(const uint32_t*)&h1;
        *(uint2*)(outp + e * 4) = pk;
    }
}

// ---------------------------------------------------------------------------
// LayerNorm over d=512 per position + transpose to channel-major output.
// ---------------------------------------------------------------------------
__global__ __launch_bounds__(256)
void ln_kernel(const float* __restrict__ X, const float* __restrict__ gamma,
               const float* __restrict__ beta, float* __restrict__ out)
{
    __shared__ float sm[16 * 513];

    const int nb   = blockIdx.x * 16;
    const int warp = threadIdx.x >> 5;
    const int lane = threadIdx.x & 31;

    for (int r = warp; r < 16; r += 8) {
        const int n = nb + r;
        const float* row = X + (size_t)n * 512;
        float v[16];
        float s = 0.f;
#pragma unroll
        for (int j = 0; j < 16; j++) { v[j] = row[lane + 32 * j]; s += v[j]; }
#pragma unroll
        for (int o = 16; o > 0; o >>= 1) s += __shfl_xor_sync(0xffffffffu, s, o);
        const float mu = s * (1.f / 512.f);
        float q = 0.f;
#pragma unroll
        for (int j = 0; j < 16; j++) { float d = v[j] - mu; q += d * d; }
#pragma unroll
        for (int o = 16; o > 0; o >>= 1) q += __shfl_xor_sync(0xffffffffu, q, o);
        const float rstd = rsqrtf(q * (1.f / 512.f) + 1e-5f);
#pragma unroll
        for (int j = 0; j < 16; j++) {
            const int o = lane + 32 * j;
            sm[r * 513 + o] = (v[j] - mu) * rstd * gamma[o] + beta[o];
        }
    }
    __syncthreads();

    const int i  = threadIdx.x & 15;
    const int ob = threadIdx.x >> 4;
    for (int o = ob; o < 512; o += 16)
        out[(size_t)o * 16384 + nb + i] = sm[i * 513 + o];
}

// ---------------------------------------------------------------------------
extern "C" void kernel_launch(void* const* d_in, const int* in_sizes, int n_in,
                              void* d_out, int out_size)
{
    const float* low   = (const float*)d_in[0];
    const float* guide = (const float*)d_in[1];
    const float* Wq    = (const float*)d_in[2];
    const float* Wk    = (const float*)d_in[3];
    const float* Wv    = (const float*)d_in[4];
    const float* Wm    = (const float*)d_in[5];
    const float* gamma = (const float*)d_in[6];
    const float* beta  = (const float*)d_in[7];
    float* out = (float*)d_out;

    __half *Af, *Lf, *Whi, *Wlo;
    float *Q, *K, *V, *M2;
    cudaGetSymbolAddress((void**)&Af,  g_Af);
    cudaGetSymbolAddress((void**)&Lf,  g_Lf);
    cudaGetSymbolAddress((void**)&Whi, g_Whi);
    cudaGetSymbolAddress((void**)&Wlo, g_Wlo);
    cudaGetSymbolAddress((void**)&Q,   g_Q);
    cudaGetSymbolAddress((void**)&K,   g_K);
    cudaGetSymbolAddress((void**)&V,   g_V);
    cudaGetSymbolAddress((void**)&M2,  g_M2);

    const int W_ELEMS = DMODEL * DMODEL;       // 262144
    const int GEMM_SMEM = NSTAGE * STAGE_B;    // 92160 B

    cudaFuncSetAttribute(mma_gemm, cudaFuncAttributeMaxDynamicSharedMemorySize,
                         GEMM_SMEM);

    // Convert + transpose activations (channel-major fp32 -> row-major fp16)
    convT_kernel<<<dim3(NPOS / 32, 16), dim3(32, 8)>>>(guide, Af, NPOS);
    convT_kernel<<<dim3(LPOS / 32, 16), dim3(32, 8)>>>(low, Lf, LPOS);

    // Convert all 4 weights in one launch: slots 0=Wq, 1=Wk, 2=Wv, 3=Wm
    conv_w_kernel<<<dim3(W_ELEMS / 4 / 256, 1, 4), 256>>>(
        (const float4*)Wq, (const float4*)Wk, (const float4*)Wv, (const float4*)Wm,
        Whi, Wlo);

    // Q, K, V projections in ONE launch (z selects; y-overrun CTAs exit)
    {
        GemmArgs gq = { Af, Whi,               Wlo,               Q, 128 };
        GemmArgs gk = { Lf, Whi + 1 * W_ELEMS, Wlo + 1 * W_ELEMS, K, 8 };
        GemmArgs gv = { Lf, Whi + 2 * W_ELEMS, Wlo + 2 * W_ELEMS, V, 8 };
        mma_gemm<<<dim3(4, 128, 3), 128, GEMM_SMEM>>>(gq, gk, gv);
    }

    // Windowed attention -> fp16 msg directly into Af (guide no longer needed)
    attn_kernel<<<dim3(32, 32), 256>>>(Q, K, V, Af);

    // M2 = msg @ Wm^T
    {
        GemmArgs gm = { Af, Whi + 3 * W_ELEMS, Wlo + 3 * W_ELEMS, M2, 128 };
        mma_gemm<<<dim3(4, 128, 1), 128, GEMM_SMEM>>>(gm, gm, gm);
    }

    // LayerNorm + transpose to channel-major output
    ln_kernel<<<1024, 256>>>(M2, gamma, beta, out);
}